// round 13
// baseline (speedup 1.0000x reference)
#include <cuda_runtime.h>
#include <cuda_bf16.h>
#include <cuda_fp16.h>
#include <stdint.h>

#define S_  2048
#define D_  1024
#define HD_ 64
#define M1_ 4096
#define BHN 32
#define SSl ((long)S_ * S_)

typedef unsigned short u16;

#define MDsz ((long)M1_ * D_)
#define DDsz ((long)D_ * D_)

// ---------------- static scratch ----------------
__device__ u16 cinh[3 * MDsz], cinl[3 * MDsz];   // converted inputs (q,k,v)
__device__ u16 winh[4 * DDsz], winl[4 * DDsz];   // converted weights (wq,wk,wv,wp)
__device__ float bias3[3 * D_];                  // gathered bq,bk,bv
__device__ u16 pjh[3 * MDsz], pjl[3 * MDsz];     // projected q,k,v (split bf16)
__device__ u16 vth[BHN * HD_ * S_], vtl[BHN * HD_ * S_];  // V^T per head
__device__ u16 athA[MDsz], atlA[MDsz];           // attn output (split bf16)
__device__ u16 g_e[(long)BHN * SSl];             // e' = exp(s - m_tile), fp16
__device__ float g_pm[BHN * 16 * S_], g_pd[BHN * 16 * S_];
__device__ float g_cm[BHN * S_], g_cd[BHN * S_];

// ---------------- helpers ----------------
__device__ __forceinline__ uint32_t smem_u32(const void* p) {
    uint32_t a;
    asm("{ .reg .u64 t; cvta.to.shared.u64 t, %1; cvt.u32.u64 %0, t; }" : "=r"(a) : "l"(p));
    return a;
}
__device__ __forceinline__ void cpa16(uint32_t d, const void* s) {
    asm volatile("cp.async.cg.shared.global [%0], [%1], 16;" :: "r"(d), "l"(s));
}
#define CPC()  asm volatile("cp.async.commit_group;" ::: "memory")
#define CPW1() asm volatile("cp.async.wait_group 1;" ::: "memory")
#define CPW0() asm volatile("cp.async.wait_group 0;" ::: "memory")

__device__ __forceinline__ void ldm_x4(uint32_t* r, uint32_t addr) {
    asm volatile("ldmatrix.sync.aligned.m8n8.x4.shared.b16 {%0,%1,%2,%3}, [%4];"
                 : "=r"(r[0]), "=r"(r[1]), "=r"(r[2]), "=r"(r[3]) : "r"(addr));
}
__device__ __forceinline__ void mma16816(float* c, const uint32_t* a, const uint32_t* b) {
    asm volatile(
        "mma.sync.aligned.m16n8k16.row.col.f32.bf16.bf16.f32 "
        "{%0,%1,%2,%3}, {%4,%5,%6,%7}, {%8,%9}, {%0,%1,%2,%3};"
        : "+f"(c[0]), "+f"(c[1]), "+f"(c[2]), "+f"(c[3])
        : "r"(a[0]), "r"(a[1]), "r"(a[2]), "r"(a[3]), "r"(b[0]), "r"(b[1]));
}
__device__ __forceinline__ uint32_t pk2(float a, float b) {
    __nv_bfloat162 t = __floats2bfloat162_rn(a, b);
    return *(uint32_t*)&t;
}
__device__ __forceinline__ void split2(float a, float b, uint32_t& h, uint32_t& l) {
    __nv_bfloat16 h0 = __float2bfloat16(a), h1 = __float2bfloat16(b);
    h = ((uint32_t)__bfloat16_as_ushort(h1) << 16) | __bfloat16_as_ushort(h0);
    l = pk2(a - __bfloat162float(h0), b - __bfloat162float(h1));
}
__device__ __forceinline__ void split4(float4 v, uint2& h, uint2& l) {
    split2(v.x, v.y, h.x, l.x);
    split2(v.z, v.w, h.y, l.y);
}

// ---------------------------------------------------------------------------
// 3-stage pipelined split-bf16 mma.sync GEMM: C[128, NT] = A[128,K] . B[NT,K]^T
//   C ~= AhBh + AhBl + AlBh (fp32 accum)
// Mainloop: wait(c) -> ONE sync -> issue(c+2) -> compute(c). The trailing
// barrier is gone: issue targets stage (c+2)%3, last read at chunk c-1 and
// separated from those readers by this iteration's sync.
// SOFTA: A = fp16 e'; p = e' * scale_j split to bf16 hi/lo via STS (2-stage);
//        the scale table for c+1 is written BEFORE the sync (gmem-only inputs)
//        so the barrier orders it against stsA(c+1)'s reads. A prologue
//        __syncthreads makes scaleS[0] visible before stsA(0) (R12's bug).
// EPI 0: fp32 out + bias; 1: scores -> fp16 e' out + column stats partials;
//     2: split-bf16 out (+bias)
// ---------------------------------------------------------------------------
template<int NT, int EPI, bool SOFTA>
__global__ __launch_bounds__(256, 2)
void mma_gemm(const u16* __restrict__ Ah, const u16* __restrict__ Al,
              const u16* __restrict__ Bh, const u16* __restrict__ Bl,
              float* __restrict__ Cf, u16* __restrict__ Ch, u16* __restrict__ Cl,
              const float* __restrict__ bias, const int* __restrict__ mask,
              const float* __restrict__ cm, const float* __restrict__ cd,
              float* __restrict__ pm, float* __restrict__ pd,
              int lda, int ldb, int ldc, int K,
              long sAb, long sAh_, long sBb, long sBh_, long sCb, long sCh_,
              long sBiasH, float scale)
{
    constexpr int WN  = NT / 2;
    constexpr int NB  = WN / 8;
    constexpr int BSZ = NT * 64;                   // bytes per B array per stage
    constexpr int NAST = SOFTA ? 2 : 3;            // A stages
    constexpr int BOFF = NAST * 16384;             // A region size
    extern __shared__ __align__(128) uint8_t sm[];
    __shared__ float scaleS[2][32];
    const uint32_t smb = smem_u32(sm);

    const int tid = threadIdx.x, wid = tid >> 5, lane = tid & 31;
    const int wm = wid >> 1, wn = wid & 1;
    const int z = blockIdx.z, bb = z >> 4, hh = z & 15;
    const int m0 = blockIdx.y * 128, n0 = blockIdx.x * NT;

    Ah += bb * sAb + hh * sAh_;
    if (!SOFTA) Al += bb * sAb + hh * sAh_;
    if (SOFTA) {
        cm += (long)z * S_;  cd += (long)z * S_;
        pm += ((long)z * 16 + blockIdx.y) * S_;
    }
    Bh += bb * sBb + hh * sBh_;  Bl += bb * sBb + hh * sBh_;
    if (EPI == 0)      { Cf += bb * sCb + hh * sCh_; }
    else if (EPI == 1) { Ch += bb * sCb + hh * sCh_; }
    else               { Ch += bb * sCb + hh * sCh_; Cl += bb * sCb + hh * sCh_; }
    if (bias) bias += hh * sBiasH;

    uint4 areg4[2];
    auto issueA = [&](int c, int s) {
#pragma unroll
        for (int p = 0; p < 2; p++) {
            const int e = p * 256 + tid, r = e >> 2, ch = e & 3;
            const uint32_t off = (uint32_t)(r * 4 + (ch ^ ((r >> 1) & 3))) * 16;
            const long src = (long)(m0 + r) * lda + c * 32 + ch * 8;
            cpa16(smb + s * 16384 + off, Ah + src);
            cpa16(smb + s * 16384 + 8192 + off, Al + src);
        }
    };
    auto issueB = [&](int c, int s) {
#pragma unroll
        for (int p = 0; p < NT * 4 / 256; p++) {
            const int e = p * 256 + tid, r = e >> 2, ch = e & 3;
            const uint32_t off = (uint32_t)(r * 4 + (ch ^ ((r >> 1) & 3))) * 16;
            const long src = (long)(n0 + r) * ldb + c * 32 + ch * 8;
            cpa16(smb + BOFF + s * 2 * BSZ + off, Bh + src);
            cpa16(smb + BOFF + s * 2 * BSZ + BSZ + off, Bl + src);
        }
    };
    auto prefA = [&](int c) {   // SOFTA: load fp16 e' tile (128 x 32)
#pragma unroll
        for (int p = 0; p < 2; p++) {
            const int e = p * 256 + tid, r = e >> 2, j8 = (e & 3) * 8;
            areg4[p] = *(const uint4*)(Ah + (long)(m0 + r) * lda + c * 32 + j8);
        }
    };
    auto stsA = [&](int c, int s) {  // SOFTA: p = e' * scale_j, split, STS
#pragma unroll
        for (int p = 0; p < 2; p++) {
            const int e = p * 256 + tid, r = e >> 2, j8 = (e & 3) * 8;
            const __half2* hp = (const __half2*)&areg4[p];
            uint4 hi, lo;
            uint32_t* hw = (uint32_t*)&hi;
            uint32_t* lw = (uint32_t*)&lo;
#pragma unroll
            for (int t = 0; t < 4; t++) {
                const float2 f = __half22float2(hp[t]);
                const float pa = f.x * scaleS[c & 1][j8 + 2 * t];
                const float pb = f.y * scaleS[c & 1][j8 + 2 * t + 1];
                split2(pa, pb, hw[t], lw[t]);
            }
            const int ch = j8 >> 3;
            const uint32_t off = (uint32_t)(r * 4 + (ch ^ ((r >> 1) & 3))) * 16;
            *(uint4*)(sm + s * 16384 + off) = hi;
            *(uint4*)(sm + s * 16384 + 8192 + off) = lo;
        }
    };

    // ldmatrix lane addressing
    const int rA = wm * 32 + (lane & 15);       // A rows
    const int cpA = (lane >> 4) & 1;
    const int swA = (rA >> 1) & 3;
    // B x4: lanes 0-7 matrix0 (nt, k-lo), 8-15 m1 (nt, k-hi),
    //       16-23 m2 (nt+1, k-lo), 24-31 m3 (nt+1, k-hi)
    const int rB4 = wn * WN + ((lane >> 4) & 1) * 8 + (lane & 7);
    const int cpB = (lane >> 3) & 1;
    const int swB = (rB4 >> 1) & 3;             // invariant under +16 row steps

    float acc[2][NB][4];
#pragma unroll
    for (int i = 0; i < 2; i++)
#pragma unroll
        for (int j = 0; j < NB; j++)
#pragma unroll
            for (int e = 0; e < 4; e++) acc[i][j][e] = 0.f;

    const int nch = K / 32;

    // ---- prologue: two chunks in flight ----
    if (SOFTA) {
        prefA(0);
        if (tid < 32)
            scaleS[0][tid] = __expf(pm[tid] - cm[tid]) / cd[tid];
    } else {
        issueA(0, 0);
    }
    issueB(0, 0);
    CPC();
    if (nch > 1) {
        if (!SOFTA) issueA(1, 1);
        issueB(1, 1);
        CPC();
    }
    // R12 bug fix: scaleS[0] (written by lanes 0-31 only) must be visible to
    // ALL threads before stsA(0) reads it in the first loop iteration.
    if (SOFTA) __syncthreads();

    for (int c = 0; c < nch; c++) {
        const int s3 = c % 3;            // B stage (and A stage when !SOFTA)
        const int sA = SOFTA ? (c & 1) : s3;

        if (c + 1 < nch) CPW1(); else CPW0();

        if (SOFTA) {
            stsA(c, sA);
            if (c + 1 < nch && tid < 32) {   // scale table for chunk c+1
                const int j = (c + 1) * 32 + tid;
                scaleS[(c + 1) & 1][tid] = __expf(pm[j] - cm[j]) / cd[j];
            }
        }
        __syncthreads();

        if (c + 2 < nch) {
            const int st = (c + 2) % 3;
            if (!SOFTA) issueA(c + 2, st);
            issueB(c + 2, st);
            CPC();
        }
        if (SOFTA && c + 1 < nch) prefA(c + 1);

        const uint32_t aBase = smb + sA * 16384;
        const uint32_t bBase = smb + BOFF + s3 * 2 * BSZ;
#pragma unroll
        for (int ks = 0; ks < 2; ks++) {
            const int cA = (2 * ks + cpA) ^ swA;
            uint32_t ah0[4], ah1[4], al0[4], al1[4];
            ldm_x4(ah0, aBase + (rA * 4 + cA) * 16);
            ldm_x4(ah1, aBase + ((rA + 16) * 4 + cA) * 16);
            ldm_x4(al0, aBase + 8192 + (rA * 4 + cA) * 16);
            ldm_x4(al1, aBase + 8192 + ((rA + 16) * 4 + cA) * 16);
            const int cB = (2 * ks + cpB) ^ swB;
#pragma unroll
            for (int nt2 = 0; nt2 < NB / 2; nt2++) {
                uint32_t bh4[4], bl4[4];
                const uint32_t ob = ((uint32_t)(rB4 + nt2 * 16) * 4 + cB) * 16;
                ldm_x4(bh4, bBase + ob);
                ldm_x4(bl4, bBase + BSZ + ob);
                const int n0t = 2 * nt2;
                mma16816(acc[0][n0t], ah0, bh4);
                mma16816(acc[0][n0t], ah0, bl4);
                mma16816(acc[0][n0t], al0, bh4);
                mma16816(acc[1][n0t], ah1, bh4);
                mma16816(acc[1][n0t], ah1, bl4);
                mma16816(acc[1][n0t], al1, bh4);
                mma16816(acc[0][n0t + 1], ah0, bh4 + 2);
                mma16816(acc[0][n0t + 1], ah0, bl4 + 2);
                mma16816(acc[0][n0t + 1], al0, bh4 + 2);
                mma16816(acc[1][n0t + 1], ah1, bh4 + 2);
                mma16816(acc[1][n0t + 1], ah1, bl4 + 2);
                mma16816(acc[1][n0t + 1], al1, bh4 + 2);
            }
        }
    }

    // ---- epilogue ----
    const int gid = lane >> 2, qid = lane & 3;
    if (EPI == 1) {
        float* smM  = (float*)(sm + BOFF + 6 * BSZ);  // [4][128]
        float* smMF = smM + 512;                      // [128]
        float* smD  = smMF + 128;                     // [4][128]

        // 1: scale + mask into acc
#pragma unroll
        for (int mt = 0; mt < 2; mt++) {
            const int r0 = m0 + wm * 32 + mt * 16 + gid;
#pragma unroll
            for (int nt = 0; nt < NB; nt++) {
                const int col = n0 + wn * WN + nt * 8 + qid * 2;
                const int2 ma = *(const int2*)(mask + (long)r0 * S_ + col);
                const int2 mb = *(const int2*)(mask + (long)(r0 + 8) * S_ + col);
                acc[mt][nt][0] = ma.x ? acc[mt][nt][0] * scale : -10000.0f;
                acc[mt][nt][1] = ma.y ? acc[mt][nt][1] * scale : -10000.0f;
                acc[mt][nt][2] = mb.x ? acc[mt][nt][2] * scale : -10000.0f;
                acc[mt][nt][3] = mb.y ? acc[mt][nt][3] * scale : -10000.0f;
            }
        }
        // 2: per-tile column max over the 128 rows
#pragma unroll
        for (int nt = 0; nt < NB; nt++) {
            float mA = fmaxf(fmaxf(acc[0][nt][0], acc[0][nt][2]),
                             fmaxf(acc[1][nt][0], acc[1][nt][2]));
            float mB = fmaxf(fmaxf(acc[0][nt][1], acc[0][nt][3]),
                             fmaxf(acc[1][nt][1], acc[1][nt][3]));
#pragma unroll
            for (int d = 4; d <= 16; d <<= 1) {
                mA = fmaxf(mA, __shfl_xor_sync(0xffffffffu, mA, d));
                mB = fmaxf(mB, __shfl_xor_sync(0xffffffffu, mB, d));
            }
            if (gid == 0) {
                const int colL = wn * WN + nt * 8 + qid * 2;
                smM[wm * 128 + colL] = mA;
                smM[wm * 128 + colL + 1] = mB;
            }
        }
        __syncthreads();
        if (tid < 128) {
            smMF[tid] = fmaxf(fmaxf(smM[tid], smM[128 + tid]),
                              fmaxf(smM[256 + tid], smM[384 + tid]));
        }
        __syncthreads();
        // 3: e' = exp(s - m_tile): store fp16 + accumulate column sums
#pragma unroll
        for (int nt = 0; nt < NB; nt++) {
            const int colL = wn * WN + nt * 8 + qid * 2;
            const float MA = smMF[colL], MB = smMF[colL + 1];
            float sA = 0.f, sB = 0.f;
#pragma unroll
            for (int mt = 0; mt < 2; mt++) {
                const int r0 = m0 + wm * 32 + mt * 16 + gid;
                const float e0 = __expf(acc[mt][nt][0] - MA);
                const float e1 = __expf(acc[mt][nt][1] - MB);
                const float e2 = __expf(acc[mt][nt][2] - MA);
                const float e3 = __expf(acc[mt][nt][3] - MB);
                sA += e0 + e2;  sB += e1 + e3;
                const __half2 p01 = __floats2half2_rn(e0, e1);
                const __half2 p23 = __floats2half2_rn(e2, e3);
                *(uint32_t*)(Ch + (long)r0 * ldc + n0 + colL) = *(const uint32_t*)&p01;
                *(uint32_t*)(Ch + (long)(r0 + 8) * ldc + n0 + colL) = *(const uint32_t*)&p23;
            }
#pragma unroll
            for (int d = 4; d <= 16; d <<= 1) {
                sA += __shfl_xor_sync(0xffffffffu, sA, d);
                sB += __shfl_xor_sync(0xffffffffu, sB, d);
            }
            if (gid == 0) {
                smD[wm * 128 + colL] = sA;
                smD[wm * 128 + colL + 1] = sB;
            }
        }
        __syncthreads();
        if (tid < 128) {
            const float Dv = smD[tid] + smD[128 + tid] + smD[256 + tid] + smD[384 + tid];
            const long o = ((long)z * 16 + blockIdx.y) * S_ + n0 + tid;
            pm[o] = smMF[tid];
            pd[o] = Dv;
        }
    } else {
#pragma unroll
        for (int mt = 0; mt < 2; mt++) {
            const int r0 = m0 + wm * 32 + mt * 16 + gid;
#pragma unroll
            for (int nt = 0; nt < NB; nt++) {
                const int col = n0 + wn * WN + nt * 8 + qid * 2;
                float2 v0 = make_float2(acc[mt][nt][0], acc[mt][nt][1]);
                float2 v1 = make_float2(acc[mt][nt][2], acc[mt][nt][3]);
                if (bias) {
                    const float b0 = bias[col], b1 = bias[col + 1];
                    v0.x += b0; v0.y += b1; v1.x += b0; v1.y += b1;
                }
                if (EPI == 0) {
                    *(float2*)(Cf + (long)r0 * ldc + col) = v0;
                    *(float2*)(Cf + (long)(r0 + 8) * ldc + col) = v1;
                } else {
                    uint32_t h0, l0, h1, l1;
                    split2(v0.x, v0.y, h0, l0);
                    split2(v1.x, v1.y, h1, l1);
                    *(uint32_t*)(Ch + (long)r0 * ldc + col) = h0;
                    *(uint32_t*)(Cl + (long)r0 * ldc + col) = l0;
                    *(uint32_t*)(Ch + (long)(r0 + 8) * ldc + col) = h1;
                    *(uint32_t*)(Cl + (long)(r0 + 8) * ldc + col) = l1;
                }
            }
        }
    }
}

// ---- fp32 -> split bf16 preconversion, multi-tensor (grid.y = segment) ----
struct Cvt4 { const float* s[4]; };

__global__ __launch_bounds__(256)
void cvt_multi(Cvt4 a, u16* __restrict__ dh, u16* __restrict__ dl, long segElems4) {
    const int seg = blockIdx.y;
    const long i = (long)blockIdx.x * 256 + threadIdx.x;
    uint2 hh, ll;
    split4(((const float4*)a.s[seg])[i], hh, ll);
    ((uint2*)(dh))[seg * segElems4 + i] = hh;
    ((uint2*)(dl))[seg * segElems4 + i] = ll;
}

// ---- gather the three projection biases into one stride-indexed array ----
__global__ __launch_bounds__(256)
void biascopy(Cvt4 a, float* __restrict__ dst) {
    const int seg = blockIdx.y;
    const int i = blockIdx.x * 256 + threadIdx.x;
    dst[seg * D_ + i] = a.s[seg][i];
}

// ---- V transpose per head (split bf16 in, split bf16 out) ----
__global__ __launch_bounds__(256)
void vtrans_kernel(const u16* __restrict__ vh, const u16* __restrict__ vl,
                   u16* __restrict__ th, u16* __restrict__ tl) {
    __shared__ uint32_t t[64][65];
    const int z = blockIdx.y, jt = blockIdx.x * 64;
    const int b = z >> 4, h = z & 15;
    const long src = ((long)b * S_ + jt) * D_ + h * HD_;
    for (int i = threadIdx.x; i < 64 * 64; i += 256) {
        const long idx = src + (long)(i >> 6) * D_ + (i & 63);
        t[i >> 6][i & 63] = (uint32_t)vh[idx] | ((uint32_t)vl[idx] << 16);
    }
    __syncthreads();
    const long dst = (long)z * HD_ * S_ + jt;
    for (int i = threadIdx.x; i < 64 * 64; i += 256) {
        const uint32_t u = t[i & 63][i >> 6];
        const long o = dst + (long)(i >> 6) * S_ + (i & 63);
        th[o] = (u16)(u & 0xFFFF);
        tl[o] = (u16)(u >> 16);
    }
}

// ---- combine column-stats partials across the 16 i-tiles ----
__global__ __launch_bounds__(256)
void redstats_kernel(const float* __restrict__ pm, const float* __restrict__ pd,
                     float* __restrict__ cm, float* __restrict__ cd) {
    const int z = blockIdx.y;
    const int j = blockIdx.x * 256 + threadIdx.x;
    float m = -3.0e38f;
#pragma unroll
    for (int it = 0; it < 16; it++)
        m = fmaxf(m, pm[((long)z * 16 + it) * S_ + j]);
    float d = 0.f;
#pragma unroll
    for (int it = 0; it < 16; it++) {
        const long o = ((long)z * 16 + it) * S_ + j;
        d += pd[o] * __expf(pm[o] - m);
    }
    cm[z * S_ + j] = m;
    cd[z * S_ + j] = d;
}

// ---------------------------------------------------------------------------
extern "C" void kernel_launch(void* const* d_in, const int* in_sizes, int n_in,
                              void* d_out, int out_size)
{
    const float* query = (const float*)d_in[0];
    const float* key_  = (const float*)d_in[1];
    const float* value = (const float*)d_in[2];
    const int*   mask  = (const int*)d_in[3];
    const float* Wq = (const float*)d_in[4];
    const float* bq = (const float*)d_in[5];
    const float* Wk = (const float*)d_in[6];
    const float* bk = (const float*)d_in[7];
    const float* Wv = (const float*)d_in[8];
    const float* bv = (const float*)d_in[9];
    const float* Wp = (const float*)d_in[10];
    const float* bp = (const float*)d_in[11];
    float* out = (float*)d_out;

    u16 *p_cinh, *p_cinl, *p_winh, *p_winl, *p_pjh, *p_pjl;
    u16 *p_vth, *p_vtl, *p_ath, *p_atl, *p_e;
    float *p_b3, *ppm, *ppd, *pcm, *pcd;
    cudaGetSymbolAddress((void**)&p_cinh, cinh); cudaGetSymbolAddress((void**)&p_cinl, cinl);
    cudaGetSymbolAddress((void**)&p_winh, winh); cudaGetSymbolAddress((void**)&p_winl, winl);
    cudaGetSymbolAddress((void**)&p_pjh, pjh);   cudaGetSymbolAddress((void**)&p_pjl, pjl);
    cudaGetSymbolAddress((void**)&p_vth, vth);   cudaGetSymbolAddress((void**)&p_vtl, vtl);
    cudaGetSymbolAddress((void**)&p_ath, athA);  cudaGetSymbolAddress((void**)&p_atl, atlA);
    cudaGetSymbolAddress((void**)&p_e, g_e);
    cudaGetSymbolAddress((void**)&p_b3, bias3);
    cudaGetSymbolAddress((void**)&ppm, g_pm);  cudaGetSymbolAddress((void**)&ppd, g_pd);
    cudaGetSymbolAddress((void**)&pcm, g_cm);  cudaGetSymbolAddress((void**)&pcd, g_cd);

    const int SM_MAIN = 3 * 16384 + 6 * 8192;            // 98304
    const int SM_SCR  = SM_MAIN + 4608;                  // 102912
    const int SM_PV   = 2 * 16384 + 6 * 4096;            // 57344
    cudaFuncSetAttribute(mma_gemm<128, 2, false>, cudaFuncAttributeMaxDynamicSharedMemorySize, SM_MAIN);
    cudaFuncSetAttribute(mma_gemm<128, 0, false>, cudaFuncAttributeMaxDynamicSharedMemorySize, SM_MAIN);
    cudaFuncSetAttribute(mma_gemm<128, 1, false>, cudaFuncAttributeMaxDynamicSharedMemorySize, SM_SCR);
    cudaFuncSetAttribute(mma_gemm<64, 2, true>,   cudaFuncAttributeMaxDynamicSharedMemorySize, SM_PV);

    const long SD  = (long)S_ * D_;
    const long HSS = 16 * SSl;

    // 1) preconvert: inputs (3 segs), weights (4 segs), biases (3 segs)
    {
        Cvt4 ain; ain.s[0] = query; ain.s[1] = key_; ain.s[2] = value; ain.s[3] = nullptr;
        cvt_multi<<<dim3(MDsz / 1024, 3), 256>>>(ain, p_cinh, p_cinl, MDsz / 4);
        Cvt4 aw; aw.s[0] = Wq; aw.s[1] = Wk; aw.s[2] = Wv; aw.s[3] = Wp;
        cvt_multi<<<dim3(DDsz / 1024, 4), 256>>>(aw, p_winh, p_winl, DDsz / 4);
        Cvt4 ab; ab.s[0] = bq; ab.s[1] = bk; ab.s[2] = bv; ab.s[3] = nullptr;
        biascopy<<<dim3(D_ / 256, 3), 256>>>(ab, p_b3);
    }

    // 2) fused Q/K/V projections: one launch, z = 0..2 selects tensor set
    mma_gemm<128, 2, false><<<dim3(D_ / 128, M1_ / 128, 3), 256, SM_MAIN>>>(
        p_cinh, p_cinl, p_winh, p_winl,
        nullptr, p_pjh, p_pjl, p_b3, nullptr, nullptr, nullptr, nullptr, nullptr,
        D_, D_, D_, D_,
        0, MDsz, 0, DDsz, 0, MDsz, D_, 0.f);

    // 3) V transpose per head (V = projection segment 2)
    vtrans_kernel<<<dim3(S_ / 64, BHN), 256>>>(p_pjh + 2 * MDsz, p_pjl + 2 * MDsz,
                                               p_vth, p_vtl);

    // 4) scores = 0.25 * q k^T, mask -> e' fp16 + column-stats partials
    mma_gemm<128, 1, false><<<dim3(S_ / 128, S_ / 128, BHN), 256, SM_SCR>>>(
        p_pjh, p_pjl, p_pjh + MDsz, p_pjl + MDsz,
        nullptr, p_e, nullptr, nullptr, mask, nullptr, nullptr, ppm, ppd,
        D_, D_, S_, HD_, SD, HD_, SD, HD_, HSS, SSl, 0, 0.25f);

    // 5) reduce partials -> cm, cd
    redstats_kernel<<<dim3(S_ / 256, BHN), 256>>>(ppm, ppd, pcm, pcd);

    // 6) attn @ V (p = e' * scale_j from smem table), split-bf16 out
    mma_gemm<64, 2, true><<<dim3(1, S_ / 128, BHN), 256, SM_PV>>>(
        p_e, nullptr, p_vth, p_vtl,
        nullptr, p_ath, p_atl, nullptr, nullptr, pcm, pcd, ppm, nullptr,
        S_, S_, D_, S_, HSS, SSl, (long)16 * HD_ * S_, (long)HD_ * S_, SD, HD_, 0, 0.f);

    // 7) output projection -> d_out (fp32 + bias, weight segment 3)
    mma_gemm<128, 0, false><<<dim3(D_ / 128, M1_ / 128, 1), 256, SM_MAIN>>>(
        p_ath, p_atl, p_winh + 3 * DDsz, p_winl + 3 * DDsz,
        out, nullptr, nullptr, bp, nullptr, nullptr, nullptr, nullptr, nullptr,
        D_, D_, D_, D_, 0, 0, 0, 0, 0, 0, 0, 0.f);
}

// round 14
// speedup vs baseline: 1.0244x; 1.0244x over previous
#include <cuda_runtime.h>
#include <cuda_bf16.h>
#include <cuda_fp16.h>
#include <stdint.h>

#define S_  2048
#define D_  1024
#define HD_ 64
#define M1_ 4096
#define BHN 32
#define SSl ((long)S_ * S_)

typedef unsigned short u16;

#define MDsz ((long)M1_ * D_)
#define DDsz ((long)D_ * D_)

// ---------------- static scratch ----------------
__device__ u16 cinh[3 * MDsz], cinl[3 * MDsz];   // converted inputs (q,k,v)
__device__ u16 winh[4 * DDsz], winl[4 * DDsz];   // converted weights (wq,wk,wv,wp)
__device__ float bias3[3 * D_];                  // gathered bq,bk,bv
__device__ u16 pjh[3 * MDsz], pjl[3 * MDsz];     // projected q,k,v (split bf16)
__device__ u16 vth[BHN * HD_ * S_], vtl[BHN * HD_ * S_];  // V^T per head
__device__ u16 athA[MDsz], atlA[MDsz];           // attn output (split bf16)
__device__ u16 g_e[(long)BHN * SSl];             // e' = exp(s - m_tile), fp16
__device__ float g_pm[BHN * 16 * S_], g_pd[BHN * 16 * S_];
__device__ float g_cm[BHN * S_], g_cd[BHN * S_];

// ---------------- helpers ----------------
__device__ __forceinline__ uint32_t smem_u32(const void* p) {
    uint32_t a;
    asm("{ .reg .u64 t; cvta.to.shared.u64 t, %1; cvt.u32.u64 %0, t; }" : "=r"(a) : "l"(p));
    return a;
}
__device__ __forceinline__ void cpa16(uint32_t d, const void* s) {
    asm volatile("cp.async.cg.shared.global [%0], [%1], 16;" :: "r"(d), "l"(s));
}
#define CPC()  asm volatile("cp.async.commit_group;" ::: "memory")
#define CPW1() asm volatile("cp.async.wait_group 1;" ::: "memory")
#define CPW0() asm volatile("cp.async.wait_group 0;" ::: "memory")

__device__ __forceinline__ void ldm_x4(uint32_t* r, uint32_t addr) {
    asm volatile("ldmatrix.sync.aligned.m8n8.x4.shared.b16 {%0,%1,%2,%3}, [%4];"
                 : "=r"(r[0]), "=r"(r[1]), "=r"(r[2]), "=r"(r[3]) : "r"(addr));
}
__device__ __forceinline__ void mma16816(float* c, const uint32_t* a, const uint32_t* b) {
    asm volatile(
        "mma.sync.aligned.m16n8k16.row.col.f32.bf16.bf16.f32 "
        "{%0,%1,%2,%3}, {%4,%5,%6,%7}, {%8,%9}, {%0,%1,%2,%3};"
        : "+f"(c[0]), "+f"(c[1]), "+f"(c[2]), "+f"(c[3])
        : "r"(a[0]), "r"(a[1]), "r"(a[2]), "r"(a[3]), "r"(b[0]), "r"(b[1]));
}
__device__ __forceinline__ uint32_t pk2(float a, float b) {
    __nv_bfloat162 t = __floats2bfloat162_rn(a, b);
    return *(uint32_t*)&t;
}
__device__ __forceinline__ void split2(float a, float b, uint32_t& h, uint32_t& l) {
    __nv_bfloat16 h0 = __float2bfloat16(a), h1 = __float2bfloat16(b);
    h = ((uint32_t)__bfloat16_as_ushort(h1) << 16) | __bfloat16_as_ushort(h0);
    l = pk2(a - __bfloat162float(h0), b - __bfloat162float(h1));
}
__device__ __forceinline__ void split4(float4 v, uint2& h, uint2& l) {
    split2(v.x, v.y, h.x, l.x);
    split2(v.z, v.w, h.y, l.y);
}

// ---------------------------------------------------------------------------
// 2-stage pipelined split-bf16 mma.sync GEMM (proven R11 structure):
//   C[128, NT] = A[128,K] . B[NT,K]^T,  C ~= AhBh + AhBl + AlBh (fp32 accum)
// SOFTA: A = fp16 e'; p = e' * scale_j, split to bf16 hi/lo via STS;
//        scale_j table (exp(pm_tile - m)/d) built by 32 lanes per chunk.
// EPI 0: fp32 out + bias; 1: scores -> fp16 e' out + column stats partials;
//     2: split-bf16 out (+bias)
// ---------------------------------------------------------------------------
template<int NT, int EPI, bool SOFTA>
__global__ __launch_bounds__(256, 2)
void mma_gemm(const u16* __restrict__ Ah, const u16* __restrict__ Al,
              const u16* __restrict__ Bh, const u16* __restrict__ Bl,
              float* __restrict__ Cf, u16* __restrict__ Ch, u16* __restrict__ Cl,
              const float* __restrict__ bias, const int* __restrict__ mask,
              const float* __restrict__ cm, const float* __restrict__ cd,
              float* __restrict__ pm, float* __restrict__ pd,
              int lda, int ldb, int ldc, int K,
              long sAb, long sAh_, long sBb, long sBh_, long sCb, long sCh_,
              long sBiasH, float scale)
{
    constexpr int WN  = NT / 2;
    constexpr int NB  = WN / 8;
    constexpr int BSZ = NT * 64;      // bytes per B array per stage
    constexpr int BOFF = 32768;       // A stages: 2 x (8K hi + 8K lo)
    extern __shared__ __align__(128) uint8_t sm[];
    __shared__ float scaleS[2][32];
    const uint32_t smb = smem_u32(sm);

    const int tid = threadIdx.x, wid = tid >> 5, lane = tid & 31;
    const int wm = wid >> 1, wn = wid & 1;
    const int z = blockIdx.z, bb = z >> 4, hh = z & 15;
    const int m0 = blockIdx.y * 128, n0 = blockIdx.x * NT;

    Ah += bb * sAb + hh * sAh_;
    if (!SOFTA) Al += bb * sAb + hh * sAh_;
    if (SOFTA) {
        cm += (long)z * S_;  cd += (long)z * S_;
        pm += ((long)z * 16 + blockIdx.y) * S_;
    }
    Bh += bb * sBb + hh * sBh_;  Bl += bb * sBb + hh * sBh_;
    if (EPI == 0)      { Cf += bb * sCb + hh * sCh_; }
    else if (EPI == 1) { Ch += bb * sCb + hh * sCh_; }
    else               { Ch += bb * sCb + hh * sCh_; Cl += bb * sCb + hh * sCh_; }
    if (bias) bias += hh * sBiasH;

    uint4 areg4[2];
    auto issueA = [&](int c, int s) {
#pragma unroll
        for (int p = 0; p < 2; p++) {
            const int e = p * 256 + tid, r = e >> 2, ch = e & 3;
            const uint32_t off = (uint32_t)(r * 4 + (ch ^ ((r >> 1) & 3))) * 16;
            const long src = (long)(m0 + r) * lda + c * 32 + ch * 8;
            cpa16(smb + s * 16384 + off, Ah + src);
            cpa16(smb + s * 16384 + 8192 + off, Al + src);
        }
    };
    auto issueB = [&](int c, int s) {
#pragma unroll
        for (int p = 0; p < NT * 4 / 256; p++) {
            const int e = p * 256 + tid, r = e >> 2, ch = e & 3;
            const uint32_t off = (uint32_t)(r * 4 + (ch ^ ((r >> 1) & 3))) * 16;
            const long src = (long)(n0 + r) * ldb + c * 32 + ch * 8;
            cpa16(smb + BOFF + s * 2 * BSZ + off, Bh + src);
            cpa16(smb + BOFF + s * 2 * BSZ + BSZ + off, Bl + src);
        }
    };
    auto prefA = [&](int c) {   // SOFTA: load fp16 e' tile (128 x 32)
#pragma unroll
        for (int p = 0; p < 2; p++) {
            const int e = p * 256 + tid, r = e >> 2, j8 = (e & 3) * 8;
            areg4[p] = *(const uint4*)(Ah + (long)(m0 + r) * lda + c * 32 + j8);
        }
    };
    auto stsA = [&](int c, int s) {  // SOFTA: p = e' * scale_j, split, STS
#pragma unroll
        for (int p = 0; p < 2; p++) {
            const int e = p * 256 + tid, r = e >> 2, j8 = (e & 3) * 8;
            const __half2* hp = (const __half2*)&areg4[p];
            uint4 hi, lo;
            uint32_t* hw = (uint32_t*)&hi;
            uint32_t* lw = (uint32_t*)&lo;
#pragma unroll
            for (int t = 0; t < 4; t++) {
                const float2 f = __half22float2(hp[t]);
                const float pa = f.x * scaleS[c & 1][j8 + 2 * t];
                const float pb = f.y * scaleS[c & 1][j8 + 2 * t + 1];
                split2(pa, pb, hw[t], lw[t]);
            }
            const int ch = j8 >> 3;
            const uint32_t off = (uint32_t)(r * 4 + (ch ^ ((r >> 1) & 3))) * 16;
            *(uint4*)(sm + s * 16384 + off) = hi;
            *(uint4*)(sm + s * 16384 + 8192 + off) = lo;
        }
    };

    // ldmatrix lane addressing
    const int rA = wm * 32 + (lane & 15);       // A rows
    const int cpA = (lane >> 4) & 1;
    const int swA = (rA >> 1) & 3;
    // B x4: lanes 0-7 matrix0 (nt, k-lo), 8-15 m1 (nt, k-hi),
    //       16-23 m2 (nt+1, k-lo), 24-31 m3 (nt+1, k-hi)
    const int rB4 = wn * WN + ((lane >> 4) & 1) * 8 + (lane & 7);
    const int cpB = (lane >> 3) & 1;
    const int swB = (rB4 >> 1) & 3;             // invariant under +16 row steps

    float acc[2][NB][4];
#pragma unroll
    for (int i = 0; i < 2; i++)
#pragma unroll
        for (int j = 0; j < NB; j++)
#pragma unroll
            for (int e = 0; e < 4; e++) acc[i][j][e] = 0.f;

    const int nch = K / 32;
    if (SOFTA) {
        prefA(0);
        if (tid < 32)
            scaleS[0][tid] = __expf(pm[tid] - cm[tid]) / cd[tid];
    } else {
        issueA(0, 0);
    }
    issueB(0, 0);
    CPC();
    if (SOFTA) __syncthreads();   // scaleS[0] visible before stsA(0)

    for (int c = 0; c < nch; c++) {
        const int s = c & 1;
        if (SOFTA) stsA(c, s);
        const bool more = (c + 1 < nch);
        if (more) {
            if (!SOFTA) issueA(c + 1, s ^ 1);
            issueB(c + 1, s ^ 1);
            CPC();
            if (SOFTA) prefA(c + 1);
            CPW1();
        } else {
            CPW0();
        }
        __syncthreads();

        if (SOFTA && more && tid < 32) {   // scale table for chunk c+1
            const int j = (c + 1) * 32 + tid;
            scaleS[s ^ 1][tid] = __expf(pm[j] - cm[j]) / cd[j];
        }

        const uint32_t aBase = smb + s * 16384;
        const uint32_t bBase = smb + BOFF + s * 2 * BSZ;
#pragma unroll
        for (int ks = 0; ks < 2; ks++) {
            const int cA = (2 * ks + cpA) ^ swA;
            uint32_t ah0[4], ah1[4], al0[4], al1[4];
            ldm_x4(ah0, aBase + (rA * 4 + cA) * 16);
            ldm_x4(ah1, aBase + ((rA + 16) * 4 + cA) * 16);
            ldm_x4(al0, aBase + 8192 + (rA * 4 + cA) * 16);
            ldm_x4(al1, aBase + 8192 + ((rA + 16) * 4 + cA) * 16);
            const int cB = (2 * ks + cpB) ^ swB;
#pragma unroll
            for (int nt2 = 0; nt2 < NB / 2; nt2++) {
                uint32_t bh4[4], bl4[4];
                const uint32_t ob = ((uint32_t)(rB4 + nt2 * 16) * 4 + cB) * 16;
                ldm_x4(bh4, bBase + ob);
                ldm_x4(bl4, bBase + BSZ + ob);
                const int n0t = 2 * nt2;
                mma16816(acc[0][n0t], ah0, bh4);
                mma16816(acc[0][n0t], ah0, bl4);
                mma16816(acc[0][n0t], al0, bh4);
                mma16816(acc[1][n0t], ah1, bh4);
                mma16816(acc[1][n0t], ah1, bl4);
                mma16816(acc[1][n0t], al1, bh4);
                mma16816(acc[0][n0t + 1], ah0, bh4 + 2);
                mma16816(acc[0][n0t + 1], ah0, bl4 + 2);
                mma16816(acc[0][n0t + 1], al0, bh4 + 2);
                mma16816(acc[1][n0t + 1], ah1, bh4 + 2);
                mma16816(acc[1][n0t + 1], ah1, bl4 + 2);
                mma16816(acc[1][n0t + 1], al1, bh4 + 2);
            }
        }
        __syncthreads();
    }

    // ---- epilogue ----
    const int gid = lane >> 2, qid = lane & 3;
    if (EPI == 1) {
        float* smM  = (float*)(sm + BOFF + 4 * BSZ);  // [4][128]
        float* smMF = smM + 512;                      // [128]
        float* smD  = smMF + 128;                     // [4][128]

        // 1: scale + mask into acc
#pragma unroll
        for (int mt = 0; mt < 2; mt++) {
            const int r0 = m0 + wm * 32 + mt * 16 + gid;
#pragma unroll
            for (int nt = 0; nt < NB; nt++) {
                const int col = n0 + wn * WN + nt * 8 + qid * 2;
                const int2 ma = *(const int2*)(mask + (long)r0 * S_ + col);
                const int2 mb = *(const int2*)(mask + (long)(r0 + 8) * S_ + col);
                acc[mt][nt][0] = ma.x ? acc[mt][nt][0] * scale : -10000.0f;
                acc[mt][nt][1] = ma.y ? acc[mt][nt][1] * scale : -10000.0f;
                acc[mt][nt][2] = mb.x ? acc[mt][nt][2] * scale : -10000.0f;
                acc[mt][nt][3] = mb.y ? acc[mt][nt][3] * scale : -10000.0f;
            }
        }
        // 2: per-tile column max over the 128 rows
#pragma unroll
        for (int nt = 0; nt < NB; nt++) {
            float mA = fmaxf(fmaxf(acc[0][nt][0], acc[0][nt][2]),
                             fmaxf(acc[1][nt][0], acc[1][nt][2]));
            float mB = fmaxf(fmaxf(acc[0][nt][1], acc[0][nt][3]),
                             fmaxf(acc[1][nt][1], acc[1][nt][3]));
#pragma unroll
            for (int d = 4; d <= 16; d <<= 1) {
                mA = fmaxf(mA, __shfl_xor_sync(0xffffffffu, mA, d));
                mB = fmaxf(mB, __shfl_xor_sync(0xffffffffu, mB, d));
            }
            if (gid == 0) {
                const int colL = wn * WN + nt * 8 + qid * 2;
                smM[wm * 128 + colL] = mA;
                smM[wm * 128 + colL + 1] = mB;
            }
        }
        __syncthreads();
        if (tid < 128) {
            smMF[tid] = fmaxf(fmaxf(smM[tid], smM[128 + tid]),
                              fmaxf(smM[256 + tid], smM[384 + tid]));
        }
        __syncthreads();
        // 3: e' = exp(s - m_tile): store fp16 + accumulate column sums
#pragma unroll
        for (int nt = 0; nt < NB; nt++) {
            const int colL = wn * WN + nt * 8 + qid * 2;
            const float MA = smMF[colL], MB = smMF[colL + 1];
            float sA = 0.f, sB = 0.f;
#pragma unroll
            for (int mt = 0; mt < 2; mt++) {
                const int r0 = m0 + wm * 32 + mt * 16 + gid;
                const float e0 = __expf(acc[mt][nt][0] - MA);
                const float e1 = __expf(acc[mt][nt][1] - MB);
                const float e2 = __expf(acc[mt][nt][2] - MA);
                const float e3 = __expf(acc[mt][nt][3] - MB);
                sA += e0 + e2;  sB += e1 + e3;
                const __half2 p01 = __floats2half2_rn(e0, e1);
                const __half2 p23 = __floats2half2_rn(e2, e3);
                *(uint32_t*)(Ch + (long)r0 * ldc + n0 + colL) = *(const uint32_t*)&p01;
                *(uint32_t*)(Ch + (long)(r0 + 8) * ldc + n0 + colL) = *(const uint32_t*)&p23;
            }
#pragma unroll
            for (int d = 4; d <= 16; d <<= 1) {
                sA += __shfl_xor_sync(0xffffffffu, sA, d);
                sB += __shfl_xor_sync(0xffffffffu, sB, d);
            }
            if (gid == 0) {
                smD[wm * 128 + colL] = sA;
                smD[wm * 128 + colL + 1] = sB;
            }
        }
        __syncthreads();
        if (tid < 128) {
            const float Dv = smD[tid] + smD[128 + tid] + smD[256 + tid] + smD[384 + tid];
            const long o = ((long)z * 16 + blockIdx.y) * S_ + n0 + tid;
            pm[o] = smMF[tid];
            pd[o] = Dv;
        }
    } else {
#pragma unroll
        for (int mt = 0; mt < 2; mt++) {
            const int r0 = m0 + wm * 32 + mt * 16 + gid;
#pragma unroll
            for (int nt = 0; nt < NB; nt++) {
                const int col = n0 + wn * WN + nt * 8 + qid * 2;
                float2 v0 = make_float2(acc[mt][nt][0], acc[mt][nt][1]);
                float2 v1 = make_float2(acc[mt][nt][2], acc[mt][nt][3]);
                if (bias) {
                    const float b0 = bias[col], b1 = bias[col + 1];
                    v0.x += b0; v0.y += b1; v1.x += b0; v1.y += b1;
                }
                if (EPI == 0) {
                    *(float2*)(Cf + (long)r0 * ldc + col) = v0;
                    *(float2*)(Cf + (long)(r0 + 8) * ldc + col) = v1;
                } else {
                    uint32_t h0, l0, h1, l1;
                    split2(v0.x, v0.y, h0, l0);
                    split2(v1.x, v1.y, h1, l1);
                    *(uint32_t*)(Ch + (long)r0 * ldc + col) = h0;
                    *(uint32_t*)(Cl + (long)r0 * ldc + col) = l0;
                    *(uint32_t*)(Ch + (long)(r0 + 8) * ldc + col) = h1;
                    *(uint32_t*)(Cl + (long)(r0 + 8) * ldc + col) = l1;
                }
            }
        }
    }
}

// ---- fp32 -> split bf16 preconversion, multi-tensor (grid.y = segment) ----
struct Cvt4 { const float* s[4]; };

__global__ __launch_bounds__(256)
void cvt_multi(Cvt4 a, u16* __restrict__ dh, u16* __restrict__ dl, long segElems4) {
    const int seg = blockIdx.y;
    const long i = (long)blockIdx.x * 256 + threadIdx.x;
    uint2 hh, ll;
    split4(((const float4*)a.s[seg])[i], hh, ll);
    ((uint2*)(dh))[seg * segElems4 + i] = hh;
    ((uint2*)(dl))[seg * segElems4 + i] = ll;
}

// ---- gather the three projection biases into one stride-indexed array ----
__global__ __launch_bounds__(256)
void biascopy(Cvt4 a, float* __restrict__ dst) {
    const int seg = blockIdx.y;
    const int i = blockIdx.x * 256 + threadIdx.x;
    dst[seg * D_ + i] = a.s[seg][i];
}

// ---- V transpose per head (split bf16 in, split bf16 out) ----
__global__ __launch_bounds__(256)
void vtrans_kernel(const u16* __restrict__ vh, const u16* __restrict__ vl,
                   u16* __restrict__ th, u16* __restrict__ tl) {
    __shared__ uint32_t t[64][65];
    const int z = blockIdx.y, jt = blockIdx.x * 64;
    const int b = z >> 4, h = z & 15;
    const long src = ((long)b * S_ + jt) * D_ + h * HD_;
    for (int i = threadIdx.x; i < 64 * 64; i += 256) {
        const long idx = src + (long)(i >> 6) * D_ + (i & 63);
        t[i >> 6][i & 63] = (uint32_t)vh[idx] | ((uint32_t)vl[idx] << 16);
    }
    __syncthreads();
    const long dst = (long)z * HD_ * S_ + jt;
    for (int i = threadIdx.x; i < 64 * 64; i += 256) {
        const uint32_t u = t[i & 63][i >> 6];
        const long o = dst + (long)(i >> 6) * S_ + (i & 63);
        th[o] = (u16)(u & 0xFFFF);
        tl[o] = (u16)(u >> 16);
    }
}

// ---- combine column-stats partials across the 16 i-tiles ----
__global__ __launch_bounds__(256)
void redstats_kernel(const float* __restrict__ pm, const float* __restrict__ pd,
                     float* __restrict__ cm, float* __restrict__ cd) {
    const int z = blockIdx.y;
    const int j = blockIdx.x * 256 + threadIdx.x;
    float m = -3.0e38f;
#pragma unroll
    for (int it = 0; it < 16; it++)
        m = fmaxf(m, pm[((long)z * 16 + it) * S_ + j]);
    float d = 0.f;
#pragma unroll
    for (int it = 0; it < 16; it++) {
        const long o = ((long)z * 16 + it) * S_ + j;
        d += pd[o] * __expf(pm[o] - m);
    }
    cm[z * S_ + j] = m;
    cd[z * S_ + j] = d;
}

// ---------------------------------------------------------------------------
extern "C" void kernel_launch(void* const* d_in, const int* in_sizes, int n_in,
                              void* d_out, int out_size)
{
    const float* query = (const float*)d_in[0];
    const float* key_  = (const float*)d_in[1];
    const float* value = (const float*)d_in[2];
    const int*   mask  = (const int*)d_in[3];
    const float* Wq = (const float*)d_in[4];
    const float* bq = (const float*)d_in[5];
    const float* Wk = (const float*)d_in[6];
    const float* bk = (const float*)d_in[7];
    const float* Wv = (const float*)d_in[8];
    const float* bv = (const float*)d_in[9];
    const float* Wp = (const float*)d_in[10];
    const float* bp = (const float*)d_in[11];
    float* out = (float*)d_out;

    u16 *p_cinh, *p_cinl, *p_winh, *p_winl, *p_pjh, *p_pjl;
    u16 *p_vth, *p_vtl, *p_ath, *p_atl, *p_e;
    float *p_b3, *ppm, *ppd, *pcm, *pcd;
    cudaGetSymbolAddress((void**)&p_cinh, cinh); cudaGetSymbolAddress((void**)&p_cinl, cinl);
    cudaGetSymbolAddress((void**)&p_winh, winh); cudaGetSymbolAddress((void**)&p_winl, winl);
    cudaGetSymbolAddress((void**)&p_pjh, pjh);   cudaGetSymbolAddress((void**)&p_pjl, pjl);
    cudaGetSymbolAddress((void**)&p_vth, vth);   cudaGetSymbolAddress((void**)&p_vtl, vtl);
    cudaGetSymbolAddress((void**)&p_ath, athA);  cudaGetSymbolAddress((void**)&p_atl, atlA);
    cudaGetSymbolAddress((void**)&p_e, g_e);
    cudaGetSymbolAddress((void**)&p_b3, bias3);
    cudaGetSymbolAddress((void**)&ppm, g_pm);  cudaGetSymbolAddress((void**)&ppd, g_pd);
    cudaGetSymbolAddress((void**)&pcm, g_cm);  cudaGetSymbolAddress((void**)&pcd, g_cd);

    const int SM_MAIN = 65536;           // NT=128 EPI 0/2
    const int SM_SCR  = 65536 + 4608;    // NT=128 EPI 1 (+stats)
    const int SM_PV   = 32768 + 16384;   // NT=64 SOFTA
    cudaFuncSetAttribute(mma_gemm<128, 2, false>, cudaFuncAttributeMaxDynamicSharedMemorySize, SM_MAIN);
    cudaFuncSetAttribute(mma_gemm<128, 0, false>, cudaFuncAttributeMaxDynamicSharedMemorySize, SM_MAIN);
    cudaFuncSetAttribute(mma_gemm<128, 1, false>, cudaFuncAttributeMaxDynamicSharedMemorySize, SM_SCR);
    cudaFuncSetAttribute(mma_gemm<64, 2, true>,   cudaFuncAttributeMaxDynamicSharedMemorySize, SM_PV);

    const long SD  = (long)S_ * D_;
    const long HSS = 16 * SSl;

    // 1) preconvert: inputs (3 segs), weights (4 segs), biases (3 segs)
    {
        Cvt4 ain; ain.s[0] = query; ain.s[1] = key_; ain.s[2] = value; ain.s[3] = nullptr;
        cvt_multi<<<dim3(MDsz / 1024, 3), 256>>>(ain, p_cinh, p_cinl, MDsz / 4);
        Cvt4 aw; aw.s[0] = Wq; aw.s[1] = Wk; aw.s[2] = Wv; aw.s[3] = Wp;
        cvt_multi<<<dim3(DDsz / 1024, 4), 256>>>(aw, p_winh, p_winl, DDsz / 4);
        Cvt4 ab; ab.s[0] = bq; ab.s[1] = bk; ab.s[2] = bv; ab.s[3] = nullptr;
        biascopy<<<dim3(D_ / 256, 3), 256>>>(ab, p_b3);
    }

    // 2) fused Q/K/V projections: one launch, z = 0..2 selects tensor set
    mma_gemm<128, 2, false><<<dim3(D_ / 128, M1_ / 128, 3), 256, SM_MAIN>>>(
        p_cinh, p_cinl, p_winh, p_winl,
        nullptr, p_pjh, p_pjl, p_b3, nullptr, nullptr, nullptr, nullptr, nullptr,
        D_, D_, D_, D_,
        0, MDsz, 0, DDsz, 0, MDsz, D_, 0.f);

    // 3) scores = 0.25 * q k^T, mask -> e' fp16 + column-stats partials
    //    (launched BEFORE vtrans: vtrans is independent and fills the
    //     scores grid's tail wave instead of sitting on the critical path)
    mma_gemm<128, 1, false><<<dim3(S_ / 128, S_ / 128, BHN), 256, SM_SCR>>>(
        p_pjh, p_pjl, p_pjh + MDsz, p_pjl + MDsz,
        nullptr, p_e, nullptr, nullptr, mask, nullptr, nullptr, ppm, ppd,
        D_, D_, S_, HD_, SD, HD_, SD, HD_, HSS, SSl, 0, 0.25f);

    // 4) V transpose per head (V = projection segment 2), overlaps scores tail
    vtrans_kernel<<<dim3(S_ / 64, BHN), 256>>>(p_pjh + 2 * MDsz, p_pjl + 2 * MDsz,
                                               p_vth, p_vtl);

    // 5) reduce partials -> cm, cd
    redstats_kernel<<<dim3(S_ / 256, BHN), 256>>>(ppm, ppd, pcm, pcd);

    // 6) attn @ V (p = e' * scale_j from smem table), split-bf16 out
    mma_gemm<64, 2, true><<<dim3(1, S_ / 128, BHN), 256, SM_PV>>>(
        p_e, nullptr, p_vth, p_vtl,
        nullptr, p_ath, p_atl, nullptr, nullptr, pcm, pcd, ppm, nullptr,
        S_, S_, D_, S_, HSS, SSl, (long)16 * HD_ * S_, (long)HD_ * S_, SD, HD_, 0, 0.f);

    // 7) output projection -> d_out (fp32 + bias, weight segment 3)
    mma_gemm<128, 0, false><<<dim3(D_ / 128, M1_ / 128, 1), 256, SM_MAIN>>>(
        p_ath, p_atl, p_winh + 3 * DDsz, p_winl + 3 * DDsz,
        out, nullptr, nullptr, bp, nullptr, nullptr, nullptr, nullptr, nullptr,
        D_, D_, D_, D_, 0, 0, 0, 0, 0, 0, 0, 0.f);
}

// round 15
// speedup vs baseline: 1.0295x; 1.0050x over previous
#include <cuda_runtime.h>
#include <cuda_bf16.h>
#include <cuda_fp16.h>
#include <stdint.h>

#define S_  2048
#define D_  1024
#define HD_ 64
#define M1_ 4096
#define BHN 32
#define SSl ((long)S_ * S_)

typedef unsigned short u16;

#define MDsz ((long)M1_ * D_)
#define DDsz ((long)D_ * D_)

// ---------------- static scratch ----------------
__device__ u16 cinh[3 * MDsz], cinl[3 * MDsz];   // converted inputs (q,k,v)
__device__ u16 winh[4 * DDsz], winl[4 * DDsz];   // converted weights (wq,wk,wv,wp)
__device__ float bias3[3 * D_];                  // gathered bq,bk,bv
__device__ u16 pjh[3 * MDsz], pjl[3 * MDsz];     // projected q,k,v (split bf16)
__device__ u16 vth[BHN * HD_ * S_], vtl[BHN * HD_ * S_];  // V^T per head
__device__ u16 athA[MDsz], atlA[MDsz];           // attn output (split bf16)
__device__ u16 g_e[(long)BHN * SSl];             // e' = exp(s - m_tile), fp16
__device__ float g_pm[BHN * 16 * S_], g_pd[BHN * 16 * S_];
__device__ float g_cm[BHN * S_], g_cd[BHN * S_];

// ---------------- helpers ----------------
__device__ __forceinline__ uint32_t smem_u32(const void* p) {
    uint32_t a;
    asm("{ .reg .u64 t; cvta.to.shared.u64 t, %1; cvt.u32.u64 %0, t; }" : "=r"(a) : "l"(p));
    return a;
}
__device__ __forceinline__ void cpa16(uint32_t d, const void* s) {
    asm volatile("cp.async.cg.shared.global [%0], [%1], 16;" :: "r"(d), "l"(s));
}
#define CPC()  asm volatile("cp.async.commit_group;" ::: "memory")
#define CPW1() asm volatile("cp.async.wait_group 1;" ::: "memory")
#define CPW0() asm volatile("cp.async.wait_group 0;" ::: "memory")

__device__ __forceinline__ void ldm_x4(uint32_t* r, uint32_t addr) {
    asm volatile("ldmatrix.sync.aligned.m8n8.x4.shared.b16 {%0,%1,%2,%3}, [%4];"
                 : "=r"(r[0]), "=r"(r[1]), "=r"(r[2]), "=r"(r[3]) : "r"(addr));
}
__device__ __forceinline__ void mma16816(float* c, const uint32_t* a, const uint32_t* b) {
    asm volatile(
        "mma.sync.aligned.m16n8k16.row.col.f32.bf16.bf16.f32 "
        "{%0,%1,%2,%3}, {%4,%5,%6,%7}, {%8,%9}, {%0,%1,%2,%3};"
        : "+f"(c[0]), "+f"(c[1]), "+f"(c[2]), "+f"(c[3])
        : "r"(a[0]), "r"(a[1]), "r"(a[2]), "r"(a[3]), "r"(b[0]), "r"(b[1]));
}
__device__ __forceinline__ uint32_t pk2(float a, float b) {
    __nv_bfloat162 t = __floats2bfloat162_rn(a, b);
    return *(uint32_t*)&t;
}
__device__ __forceinline__ void split2(float a, float b, uint32_t& h, uint32_t& l) {
    __nv_bfloat16 h0 = __float2bfloat16(a), h1 = __float2bfloat16(b);
    h = ((uint32_t)__bfloat16_as_ushort(h1) << 16) | __bfloat16_as_ushort(h0);
    l = pk2(a - __bfloat162float(h0), b - __bfloat162float(h1));
}
__device__ __forceinline__ void split4(float4 v, uint2& h, uint2& l) {
    split2(v.x, v.y, h.x, l.x);
    split2(v.z, v.w, h.y, l.y);
}

// ---------------------------------------------------------------------------
// 2-stage pipelined split-bf16 mma.sync GEMM (proven R11 structure), with the
// 12 HMMAs per nt2 iteration reordered into 3 waves (hh, hl, lh) across the 4
// accumulators: same-accumulator RAW reuse distance 1 -> 4 to cover HMMA
// latency. Per-accumulator term order (hh, hl, lh) is preserved, so the fp32
// result is bit-identical to R11.
//   C[128, NT] = A[128,K] . B[NT,K]^T,  C ~= AhBh + AhBl + AlBh (fp32 accum)
// SOFTA: A = fp16 e'; p = e' * scale_j, split to bf16 hi/lo via STS;
//        scale_j table (exp(pm_tile - m)/d) built by 32 lanes per chunk.
// EPI 0: fp32 out + bias; 1: scores -> fp16 e' out + column stats partials;
//     2: split-bf16 out (+bias)
// ---------------------------------------------------------------------------
template<int NT, int EPI, bool SOFTA>
__global__ __launch_bounds__(256, 2)
void mma_gemm(const u16* __restrict__ Ah, const u16* __restrict__ Al,
              const u16* __restrict__ Bh, const u16* __restrict__ Bl,
              float* __restrict__ Cf, u16* __restrict__ Ch, u16* __restrict__ Cl,
              const float* __restrict__ bias, const int* __restrict__ mask,
              const float* __restrict__ cm, const float* __restrict__ cd,
              float* __restrict__ pm, float* __restrict__ pd,
              int lda, int ldb, int ldc, int K,
              long sAb, long sAh_, long sBb, long sBh_, long sCb, long sCh_,
              long sBiasH, float scale)
{
    constexpr int WN  = NT / 2;
    constexpr int NB  = WN / 8;
    constexpr int BSZ = NT * 64;      // bytes per B array per stage
    constexpr int BOFF = 32768;       // A stages: 2 x (8K hi + 8K lo)
    extern __shared__ __align__(128) uint8_t sm[];
    __shared__ float scaleS[2][32];
    const uint32_t smb = smem_u32(sm);

    const int tid = threadIdx.x, wid = tid >> 5, lane = tid & 31;
    const int wm = wid >> 1, wn = wid & 1;
    const int z = blockIdx.z, bb = z >> 4, hh = z & 15;
    const int m0 = blockIdx.y * 128, n0 = blockIdx.x * NT;

    Ah += bb * sAb + hh * sAh_;
    if (!SOFTA) Al += bb * sAb + hh * sAh_;
    if (SOFTA) {
        cm += (long)z * S_;  cd += (long)z * S_;
        pm += ((long)z * 16 + blockIdx.y) * S_;
    }
    Bh += bb * sBb + hh * sBh_;  Bl += bb * sBb + hh * sBh_;
    if (EPI == 0)      { Cf += bb * sCb + hh * sCh_; }
    else if (EPI == 1) { Ch += bb * sCb + hh * sCh_; }
    else               { Ch += bb * sCb + hh * sCh_; Cl += bb * sCb + hh * sCh_; }
    if (bias) bias += hh * sBiasH;

    uint4 areg4[2];
    auto issueA = [&](int c, int s) {
#pragma unroll
        for (int p = 0; p < 2; p++) {
            const int e = p * 256 + tid, r = e >> 2, ch = e & 3;
            const uint32_t off = (uint32_t)(r * 4 + (ch ^ ((r >> 1) & 3))) * 16;
            const long src = (long)(m0 + r) * lda + c * 32 + ch * 8;
            cpa16(smb + s * 16384 + off, Ah + src);
            cpa16(smb + s * 16384 + 8192 + off, Al + src);
        }
    };
    auto issueB = [&](int c, int s) {
#pragma unroll
        for (int p = 0; p < NT * 4 / 256; p++) {
            const int e = p * 256 + tid, r = e >> 2, ch = e & 3;
            const uint32_t off = (uint32_t)(r * 4 + (ch ^ ((r >> 1) & 3))) * 16;
            const long src = (long)(n0 + r) * ldb + c * 32 + ch * 8;
            cpa16(smb + BOFF + s * 2 * BSZ + off, Bh + src);
            cpa16(smb + BOFF + s * 2 * BSZ + BSZ + off, Bl + src);
        }
    };
    auto prefA = [&](int c) {   // SOFTA: load fp16 e' tile (128 x 32)
#pragma unroll
        for (int p = 0; p < 2; p++) {
            const int e = p * 256 + tid, r = e >> 2, j8 = (e & 3) * 8;
            areg4[p] = *(const uint4*)(Ah + (long)(m0 + r) * lda + c * 32 + j8);
        }
    };
    auto stsA = [&](int c, int s) {  // SOFTA: p = e' * scale_j, split, STS
#pragma unroll
        for (int p = 0; p < 2; p++) {
            const int e = p * 256 + tid, r = e >> 2, j8 = (e & 3) * 8;
            const __half2* hp = (const __half2*)&areg4[p];
            uint4 hi, lo;
            uint32_t* hw = (uint32_t*)&hi;
            uint32_t* lw = (uint32_t*)&lo;
#pragma unroll
            for (int t = 0; t < 4; t++) {
                const float2 f = __half22float2(hp[t]);
                const float pa = f.x * scaleS[c & 1][j8 + 2 * t];
                const float pb = f.y * scaleS[c & 1][j8 + 2 * t + 1];
                split2(pa, pb, hw[t], lw[t]);
            }
            const int ch = j8 >> 3;
            const uint32_t off = (uint32_t)(r * 4 + (ch ^ ((r >> 1) & 3))) * 16;
            *(uint4*)(sm + s * 16384 + off) = hi;
            *(uint4*)(sm + s * 16384 + 8192 + off) = lo;
        }
    };

    // ldmatrix lane addressing
    const int rA = wm * 32 + (lane & 15);       // A rows
    const int cpA = (lane >> 4) & 1;
    const int swA = (rA >> 1) & 3;
    // B x4: lanes 0-7 matrix0 (nt, k-lo), 8-15 m1 (nt, k-hi),
    //       16-23 m2 (nt+1, k-lo), 24-31 m3 (nt+1, k-hi)
    const int rB4 = wn * WN + ((lane >> 4) & 1) * 8 + (lane & 7);
    const int cpB = (lane >> 3) & 1;
    const int swB = (rB4 >> 1) & 3;             // invariant under +16 row steps

    float acc[2][NB][4];
#pragma unroll
    for (int i = 0; i < 2; i++)
#pragma unroll
        for (int j = 0; j < NB; j++)
#pragma unroll
            for (int e = 0; e < 4; e++) acc[i][j][e] = 0.f;

    const int nch = K / 32;
    if (SOFTA) {
        prefA(0);
        if (tid < 32)
            scaleS[0][tid] = __expf(pm[tid] - cm[tid]) / cd[tid];
    } else {
        issueA(0, 0);
    }
    issueB(0, 0);
    CPC();
    if (SOFTA) __syncthreads();   // scaleS[0] visible before stsA(0)

    for (int c = 0; c < nch; c++) {
        const int s = c & 1;
        if (SOFTA) stsA(c, s);
        const bool more = (c + 1 < nch);
        if (more) {
            if (!SOFTA) issueA(c + 1, s ^ 1);
            issueB(c + 1, s ^ 1);
            CPC();
            if (SOFTA) prefA(c + 1);
            CPW1();
        } else {
            CPW0();
        }
        __syncthreads();

        if (SOFTA && more && tid < 32) {   // scale table for chunk c+1
            const int j = (c + 1) * 32 + tid;
            scaleS[s ^ 1][tid] = __expf(pm[j] - cm[j]) / cd[j];
        }

        const uint32_t aBase = smb + s * 16384;
        const uint32_t bBase = smb + BOFF + s * 2 * BSZ;
#pragma unroll
        for (int ks = 0; ks < 2; ks++) {
            const int cA = (2 * ks + cpA) ^ swA;
            uint32_t ah0[4], ah1[4], al0[4], al1[4];
            ldm_x4(ah0, aBase + (rA * 4 + cA) * 16);
            ldm_x4(ah1, aBase + ((rA + 16) * 4 + cA) * 16);
            ldm_x4(al0, aBase + 8192 + (rA * 4 + cA) * 16);
            ldm_x4(al1, aBase + 8192 + ((rA + 16) * 4 + cA) * 16);
            const int cB = (2 * ks + cpB) ^ swB;
#pragma unroll
            for (int nt2 = 0; nt2 < NB / 2; nt2++) {
                uint32_t bh4[4], bl4[4];
                const uint32_t ob = ((uint32_t)(rB4 + nt2 * 16) * 4 + cB) * 16;
                ldm_x4(bh4, bBase + ob);
                ldm_x4(bl4, bBase + BSZ + ob);
                const int n0t = 2 * nt2;
                // wave 1: hh across all 4 accumulators
                mma16816(acc[0][n0t],     ah0, bh4);
                mma16816(acc[1][n0t],     ah1, bh4);
                mma16816(acc[0][n0t + 1], ah0, bh4 + 2);
                mma16816(acc[1][n0t + 1], ah1, bh4 + 2);
                // wave 2: hl
                mma16816(acc[0][n0t],     ah0, bl4);
                mma16816(acc[1][n0t],     ah1, bl4);
                mma16816(acc[0][n0t + 1], ah0, bl4 + 2);
                mma16816(acc[1][n0t + 1], ah1, bl4 + 2);
                // wave 3: lh
                mma16816(acc[0][n0t],     al0, bh4);
                mma16816(acc[1][n0t],     al1, bh4);
                mma16816(acc[0][n0t + 1], al0, bh4 + 2);
                mma16816(acc[1][n0t + 1], al1, bh4 + 2);
            }
        }
        __syncthreads();
    }

    // ---- epilogue ----
    const int gid = lane >> 2, qid = lane & 3;
    if (EPI == 1) {
        float* smM  = (float*)(sm + BOFF + 4 * BSZ);  // [4][128]
        float* smMF = smM + 512;                      // [128]
        float* smD  = smMF + 128;                     // [4][128]

        // 1: scale + mask into acc
#pragma unroll
        for (int mt = 0; mt < 2; mt++) {
            const int r0 = m0 + wm * 32 + mt * 16 + gid;
#pragma unroll
            for (int nt = 0; nt < NB; nt++) {
                const int col = n0 + wn * WN + nt * 8 + qid * 2;
                const int2 ma = *(const int2*)(mask + (long)r0 * S_ + col);
                const int2 mb = *(const int2*)(mask + (long)(r0 + 8) * S_ + col);
                acc[mt][nt][0] = ma.x ? acc[mt][nt][0] * scale : -10000.0f;
                acc[mt][nt][1] = ma.y ? acc[mt][nt][1] * scale : -10000.0f;
                acc[mt][nt][2] = mb.x ? acc[mt][nt][2] * scale : -10000.0f;
                acc[mt][nt][3] = mb.y ? acc[mt][nt][3] * scale : -10000.0f;
            }
        }
        // 2: per-tile column max over the 128 rows
#pragma unroll
        for (int nt = 0; nt < NB; nt++) {
            float mA = fmaxf(fmaxf(acc[0][nt][0], acc[0][nt][2]),
                             fmaxf(acc[1][nt][0], acc[1][nt][2]));
            float mB = fmaxf(fmaxf(acc[0][nt][1], acc[0][nt][3]),
                             fmaxf(acc[1][nt][1], acc[1][nt][3]));
#pragma unroll
            for (int d = 4; d <= 16; d <<= 1) {
                mA = fmaxf(mA, __shfl_xor_sync(0xffffffffu, mA, d));
                mB = fmaxf(mB, __shfl_xor_sync(0xffffffffu, mB, d));
            }
            if (gid == 0) {
                const int colL = wn * WN + nt * 8 + qid * 2;
                smM[wm * 128 + colL] = mA;
                smM[wm * 128 + colL + 1] = mB;
            }
        }
        __syncthreads();
        if (tid < 128) {
            smMF[tid] = fmaxf(fmaxf(smM[tid], smM[128 + tid]),
                              fmaxf(smM[256 + tid], smM[384 + tid]));
        }
        __syncthreads();
        // 3: e' = exp(s - m_tile): store fp16 + accumulate column sums
#pragma unroll
        for (int nt = 0; nt < NB; nt++) {
            const int colL = wn * WN + nt * 8 + qid * 2;
            const float MA = smMF[colL], MB = smMF[colL + 1];
            float sA = 0.f, sB = 0.f;
#pragma unroll
            for (int mt = 0; mt < 2; mt++) {
                const int r0 = m0 + wm * 32 + mt * 16 + gid;
                const float e0 = __expf(acc[mt][nt][0] - MA);
                const float e1 = __expf(acc[mt][nt][1] - MB);
                const float e2 = __expf(acc[mt][nt][2] - MA);
                const float e3 = __expf(acc[mt][nt][3] - MB);
                sA += e0 + e2;  sB += e1 + e3;
                const __half2 p01 = __floats2half2_rn(e0, e1);
                const __half2 p23 = __floats2half2_rn(e2, e3);
                *(uint32_t*)(Ch + (long)r0 * ldc + n0 + colL) = *(const uint32_t*)&p01;
                *(uint32_t*)(Ch + (long)(r0 + 8) * ldc + n0 + colL) = *(const uint32_t*)&p23;
            }
#pragma unroll
            for (int d = 4; d <= 16; d <<= 1) {
                sA += __shfl_xor_sync(0xffffffffu, sA, d);
                sB += __shfl_xor_sync(0xffffffffu, sB, d);
            }
            if (gid == 0) {
                smD[wm * 128 + colL] = sA;
                smD[wm * 128 + colL + 1] = sB;
            }
        }
        __syncthreads();
        if (tid < 128) {
            const float Dv = smD[tid] + smD[128 + tid] + smD[256 + tid] + smD[384 + tid];
            const long o = ((long)z * 16 + blockIdx.y) * S_ + n0 + tid;
            pm[o] = smMF[tid];
            pd[o] = Dv;
        }
    } else {
#pragma unroll
        for (int mt = 0; mt < 2; mt++) {
            const int r0 = m0 + wm * 32 + mt * 16 + gid;
#pragma unroll
            for (int nt = 0; nt < NB; nt++) {
                const int col = n0 + wn * WN + nt * 8 + qid * 2;
                float2 v0 = make_float2(acc[mt][nt][0], acc[mt][nt][1]);
                float2 v1 = make_float2(acc[mt][nt][2], acc[mt][nt][3]);
                if (bias) {
                    const float b0 = bias[col], b1 = bias[col + 1];
                    v0.x += b0; v0.y += b1; v1.x += b0; v1.y += b1;
                }
                if (EPI == 0) {
                    *(float2*)(Cf + (long)r0 * ldc + col) = v0;
                    *(float2*)(Cf + (long)(r0 + 8) * ldc + col) = v1;
                } else {
                    uint32_t h0, l0, h1, l1;
                    split2(v0.x, v0.y, h0, l0);
                    split2(v1.x, v1.y, h1, l1);
                    *(uint32_t*)(Ch + (long)r0 * ldc + col) = h0;
                    *(uint32_t*)(Cl + (long)r0 * ldc + col) = l0;
                    *(uint32_t*)(Ch + (long)(r0 + 8) * ldc + col) = h1;
                    *(uint32_t*)(Cl + (long)(r0 + 8) * ldc + col) = l1;
                }
            }
        }
    }
}

// ---- fp32 -> split bf16 preconversion, multi-tensor (grid.y = segment) ----
struct Cvt4 { const float* s[4]; };

__global__ __launch_bounds__(256)
void cvt_multi(Cvt4 a, u16* __restrict__ dh, u16* __restrict__ dl, long segElems4) {
    const int seg = blockIdx.y;
    const long i = (long)blockIdx.x * 256 + threadIdx.x;
    uint2 hh, ll;
    split4(((const float4*)a.s[seg])[i], hh, ll);
    ((uint2*)(dh))[seg * segElems4 + i] = hh;
    ((uint2*)(dl))[seg * segElems4 + i] = ll;
}

// ---- gather the three projection biases into one stride-indexed array ----
__global__ __launch_bounds__(256)
void biascopy(Cvt4 a, float* __restrict__ dst) {
    const int seg = blockIdx.y;
    const int i = blockIdx.x * 256 + threadIdx.x;
    dst[seg * D_ + i] = a.s[seg][i];
}

// ---- V transpose per head (split bf16 in, split bf16 out) ----
__global__ __launch_bounds__(256)
void vtrans_kernel(const u16* __restrict__ vh, const u16* __restrict__ vl,
                   u16* __restrict__ th, u16* __restrict__ tl) {
    __shared__ uint32_t t[64][65];
    const int z = blockIdx.y, jt = blockIdx.x * 64;
    const int b = z >> 4, h = z & 15;
    const long src = ((long)b * S_ + jt) * D_ + h * HD_;
    for (int i = threadIdx.x; i < 64 * 64; i += 256) {
        const long idx = src + (long)(i >> 6) * D_ + (i & 63);
        t[i >> 6][i & 63] = (uint32_t)vh[idx] | ((uint32_t)vl[idx] << 16);
    }
    __syncthreads();
    const long dst = (long)z * HD_ * S_ + jt;
    for (int i = threadIdx.x; i < 64 * 64; i += 256) {
        const uint32_t u = t[i & 63][i >> 6];
        const long o = dst + (long)(i >> 6) * S_ + (i & 63);
        th[o] = (u16)(u & 0xFFFF);
        tl[o] = (u16)(u >> 16);
    }
}

// ---- combine column-stats partials across the 16 i-tiles ----
__global__ __launch_bounds__(256)
void redstats_kernel(const float* __restrict__ pm, const float* __restrict__ pd,
                     float* __restrict__ cm, float* __restrict__ cd) {
    const int z = blockIdx.y;
    const int j = blockIdx.x * 256 + threadIdx.x;
    float m = -3.0e38f;
#pragma unroll
    for (int it = 0; it < 16; it++)
        m = fmaxf(m, pm[((long)z * 16 + it) * S_ + j]);
    float d = 0.f;
#pragma unroll
    for (int it = 0; it < 16; it++) {
        const long o = ((long)z * 16 + it) * S_ + j;
        d += pd[o] * __expf(pm[o] - m);
    }
    cm[z * S_ + j] = m;
    cd[z * S_ + j] = d;
}

// ---------------------------------------------------------------------------
extern "C" void kernel_launch(void* const* d_in, const int* in_sizes, int n_in,
                              void* d_out, int out_size)
{
    const float* query = (const float*)d_in[0];
    const float* key_  = (const float*)d_in[1];
    const float* value = (const float*)d_in[2];
    const int*   mask  = (const int*)d_in[3];
    const float* Wq = (const float*)d_in[4];
    const float* bq = (const float*)d_in[5];
    const float* Wk = (const float*)d_in[6];
    const float* bk = (const float*)d_in[7];
    const float* Wv = (const float*)d_in[8];
    const float* bv = (const float*)d_in[9];
    const float* Wp = (const float*)d_in[10];
    const float* bp = (const float*)d_in[11];
    float* out = (float*)d_out;

    u16 *p_cinh, *p_cinl, *p_winh, *p_winl, *p_pjh, *p_pjl;
    u16 *p_vth, *p_vtl, *p_ath, *p_atl, *p_e;
    float *p_b3, *ppm, *ppd, *pcm, *pcd;
    cudaGetSymbolAddress((void**)&p_cinh, cinh); cudaGetSymbolAddress((void**)&p_cinl, cinl);
    cudaGetSymbolAddress((void**)&p_winh, winh); cudaGetSymbolAddress((void**)&p_winl, winl);
    cudaGetSymbolAddress((void**)&p_pjh, pjh);   cudaGetSymbolAddress((void**)&p_pjl, pjl);
    cudaGetSymbolAddress((void**)&p_vth, vth);   cudaGetSymbolAddress((void**)&p_vtl, vtl);
    cudaGetSymbolAddress((void**)&p_ath, athA);  cudaGetSymbolAddress((void**)&p_atl, atlA);
    cudaGetSymbolAddress((void**)&p_e, g_e);
    cudaGetSymbolAddress((void**)&p_b3, bias3);
    cudaGetSymbolAddress((void**)&ppm, g_pm);  cudaGetSymbolAddress((void**)&ppd, g_pd);
    cudaGetSymbolAddress((void**)&pcm, g_cm);  cudaGetSymbolAddress((void**)&pcd, g_cd);

    const int SM_MAIN = 65536;           // NT=128 EPI 0/2
    const int SM_SCR  = 65536 + 4608;    // NT=128 EPI 1 (+stats)
    const int SM_PV   = 32768 + 16384;   // NT=64 SOFTA
    cudaFuncSetAttribute(mma_gemm<128, 2, false>, cudaFuncAttributeMaxDynamicSharedMemorySize, SM_MAIN);
    cudaFuncSetAttribute(mma_gemm<128, 0, false>, cudaFuncAttributeMaxDynamicSharedMemorySize, SM_MAIN);
    cudaFuncSetAttribute(mma_gemm<128, 1, false>, cudaFuncAttributeMaxDynamicSharedMemorySize, SM_SCR);
    cudaFuncSetAttribute(mma_gemm<64, 2, true>,   cudaFuncAttributeMaxDynamicSharedMemorySize, SM_PV);

    const long SD  = (long)S_ * D_;
    const long HSS = 16 * SSl;

    // 1) preconvert: inputs (3 segs), weights (4 segs), biases (3 segs)
    {
        Cvt4 ain; ain.s[0] = query; ain.s[1] = key_; ain.s[2] = value; ain.s[3] = nullptr;
        cvt_multi<<<dim3(MDsz / 1024, 3), 256>>>(ain, p_cinh, p_cinl, MDsz / 4);
        Cvt4 aw; aw.s[0] = Wq; aw.s[1] = Wk; aw.s[2] = Wv; aw.s[3] = Wp;
        cvt_multi<<<dim3(DDsz / 1024, 4), 256>>>(aw, p_winh, p_winl, DDsz / 4);
        Cvt4 ab; ab.s[0] = bq; ab.s[1] = bk; ab.s[2] = bv; ab.s[3] = nullptr;
        biascopy<<<dim3(D_ / 256, 3), 256>>>(ab, p_b3);
    }

    // 2) fused Q/K/V projections: one launch, z = 0..2 selects tensor set
    mma_gemm<128, 2, false><<<dim3(D_ / 128, M1_ / 128, 3), 256, SM_MAIN>>>(
        p_cinh, p_cinl, p_winh, p_winl,
        nullptr, p_pjh, p_pjl, p_b3, nullptr, nullptr, nullptr, nullptr, nullptr,
        D_, D_, D_, D_,
        0, MDsz, 0, DDsz, 0, MDsz, D_, 0.f);

    // 3) V transpose per head (V = projection segment 2)
    vtrans_kernel<<<dim3(S_ / 64, BHN), 256>>>(p_pjh + 2 * MDsz, p_pjl + 2 * MDsz,
                                               p_vth, p_vtl);

    // 4) scores = 0.25 * q k^T, mask -> e' fp16 + column-stats partials
    mma_gemm<128, 1, false><<<dim3(S_ / 128, S_ / 128, BHN), 256, SM_SCR>>>(
        p_pjh, p_pjl, p_pjh + MDsz, p_pjl + MDsz,
        nullptr, p_e, nullptr, nullptr, mask, nullptr, nullptr, ppm, ppd,
        D_, D_, S_, HD_, SD, HD_, SD, HD_, HSS, SSl, 0, 0.25f);

    // 5) reduce partials -> cm, cd
    redstats_kernel<<<dim3(S_ / 256, BHN), 256>>>(ppm, ppd, pcm, pcd);

    // 6) attn @ V (p = e' * scale_j from smem table), split-bf16 out
    mma_gemm<64, 2, true><<<dim3(1, S_ / 128, BHN), 256, SM_PV>>>(
        p_e, nullptr, p_vth, p_vtl,
        nullptr, p_ath, p_atl, nullptr, nullptr, pcm, pcd, ppm, nullptr,
        S_, S_, D_, S_, HSS, SSl, (long)16 * HD_ * S_, (long)HD_ * S_, SD, HD_, 0, 0.f);

    // 7) output projection -> d_out (fp32 + bias, weight segment 3)
    mma_gemm<128, 0, false><<<dim3(D_ / 128, M1_ / 128, 1), 256, SM_MAIN>>>(
        p_ath, p_atl, p_winh + 3 * DDsz, p_winl + 3 * DDsz,
        out, nullptr, nullptr, bp, nullptr, nullptr, nullptr, nullptr, nullptr,
        D_, D_, D_, D_, 0, 0, 0, 0, 0, 0, 0, 0.f);
}

// round 16
// speedup vs baseline: 1.0799x; 1.0490x over previous
#include <cuda_runtime.h>
#include <cuda_bf16.h>
#include <cuda_fp16.h>
#include <stdint.h>

#define S_  2048
#define D_  1024
#define HD_ 64
#define M1_ 4096
#define BHN 32
#define SSl ((long)S_ * S_)

typedef unsigned short u16;

#define MDsz ((long)M1_ * D_)
#define DDsz ((long)D_ * D_)

// ---------------- static scratch ----------------
__device__ u16 cinh[3 * MDsz], cinl[3 * MDsz];   // converted inputs (q,k,v)
__device__ u16 winh[4 * DDsz], winl[4 * DDsz];   // converted weights (wq,wk,wv,wp)
__device__ float bias3[3 * D_];                  // gathered bq,bk,bv
__device__ u16 pjh[3 * MDsz], pjl[3 * MDsz];     // projected q,k,v (split bf16)
__device__ u16 vth[BHN * HD_ * S_], vtl[BHN * HD_ * S_];  // V^T per head (split FP16)
__device__ u16 athA[MDsz], atlA[MDsz];           // attn output (split bf16)
__device__ u16 g_e[(long)BHN * SSl];             // e' = exp(s - m_tile), fp16
__device__ float g_pm[BHN * 16 * S_], g_pd[BHN * 16 * S_];
__device__ float g_cm[BHN * S_], g_cd[BHN * S_];

// ---------------- helpers ----------------
__device__ __forceinline__ uint32_t smem_u32(const void* p) {
    uint32_t a;
    asm("{ .reg .u64 t; cvta.to.shared.u64 t, %1; cvt.u32.u64 %0, t; }" : "=r"(a) : "l"(p));
    return a;
}
__device__ __forceinline__ void cpa16(uint32_t d, const void* s) {
    asm volatile("cp.async.cg.shared.global [%0], [%1], 16;" :: "r"(d), "l"(s));
}
#define CPC()  asm volatile("cp.async.commit_group;" ::: "memory")
#define CPW1() asm volatile("cp.async.wait_group 1;" ::: "memory")
#define CPW0() asm volatile("cp.async.wait_group 0;" ::: "memory")

__device__ __forceinline__ void ldm_x4(uint32_t* r, uint32_t addr) {
    asm volatile("ldmatrix.sync.aligned.m8n8.x4.shared.b16 {%0,%1,%2,%3}, [%4];"
                 : "=r"(r[0]), "=r"(r[1]), "=r"(r[2]), "=r"(r[3]) : "r"(addr));
}
__device__ __forceinline__ void mma16816(float* c, const uint32_t* a, const uint32_t* b) {
    asm volatile(
        "mma.sync.aligned.m16n8k16.row.col.f32.bf16.bf16.f32 "
        "{%0,%1,%2,%3}, {%4,%5,%6,%7}, {%8,%9}, {%0,%1,%2,%3};"
        : "+f"(c[0]), "+f"(c[1]), "+f"(c[2]), "+f"(c[3])
        : "r"(a[0]), "r"(a[1]), "r"(a[2]), "r"(a[3]), "r"(b[0]), "r"(b[1]));
}
__device__ __forceinline__ void mma_fp(float* c, const uint32_t* a, const uint32_t* b) {
    asm volatile(
        "mma.sync.aligned.m16n8k16.row.col.f32.f16.f16.f32 "
        "{%0,%1,%2,%3}, {%4,%5,%6,%7}, {%8,%9}, {%0,%1,%2,%3};"
        : "+f"(c[0]), "+f"(c[1]), "+f"(c[2]), "+f"(c[3])
        : "r"(a[0]), "r"(a[1]), "r"(a[2]), "r"(a[3]), "r"(b[0]), "r"(b[1]));
}
__device__ __forceinline__ uint32_t pk2(float a, float b) {
    __nv_bfloat162 t = __floats2bfloat162_rn(a, b);
    return *(uint32_t*)&t;
}
__device__ __forceinline__ void split2(float a, float b, uint32_t& h, uint32_t& l) {
    __nv_bfloat16 h0 = __float2bfloat16(a), h1 = __float2bfloat16(b);
    h = ((uint32_t)__bfloat16_as_ushort(h1) << 16) | __bfloat16_as_ushort(h0);
    l = pk2(a - __bfloat162float(h0), b - __bfloat162float(h1));
}
__device__ __forceinline__ void split4(float4 v, uint2& h, uint2& l) {
    split2(v.x, v.y, h.x, l.x);
    split2(v.z, v.w, h.y, l.y);
}

// ---------------------------------------------------------------------------
// 2-stage pipelined mma.sync GEMM (proven R11 structure).
// !SOFTA (bf16 3-term): C ~= AhBh + AhBl + AlBh, A/B preconverted split-bf16.
// SOFTA  (fp16 2-term): A = fp16 e' (in Ah); p = fp16(e' * scale_j), single
//        operand; B = V^T split fp16; C ~= A(Bh + Bl).  PV work -33%.
// EPI 0: fp32 out + bias; 1: scores -> fp16 e' out + column stats partials;
//     2: split-bf16 out (+bias)
// ---------------------------------------------------------------------------
template<int NT, int EPI, bool SOFTA>
__global__ __launch_bounds__(256, 2)
void mma_gemm(const u16* __restrict__ Ah, const u16* __restrict__ Al,
              const u16* __restrict__ Bh, const u16* __restrict__ Bl,
              float* __restrict__ Cf, u16* __restrict__ Ch, u16* __restrict__ Cl,
              const float* __restrict__ bias, const int* __restrict__ mask,
              const float* __restrict__ cm, const float* __restrict__ cd,
              float* __restrict__ pm, float* __restrict__ pd,
              int lda, int ldb, int ldc, int K,
              long sAb, long sAh_, long sBb, long sBh_, long sCb, long sCh_,
              long sBiasH, float scale)
{
    constexpr int WN  = NT / 2;
    constexpr int NB  = WN / 8;
    constexpr int BSZ = NT * 64;                   // bytes per B array per stage
    constexpr int ASTG = SOFTA ? 8192 : 16384;     // A bytes per stage
    constexpr int BOFF = 2 * ASTG;                 // A region size
    extern __shared__ __align__(128) uint8_t sm[];
    __shared__ float scaleS[2][32];
    const uint32_t smb = smem_u32(sm);

    const int tid = threadIdx.x, wid = tid >> 5, lane = tid & 31;
    const int wm = wid >> 1, wn = wid & 1;
    const int z = blockIdx.z, bb = z >> 4, hh = z & 15;
    const int m0 = blockIdx.y * 128, n0 = blockIdx.x * NT;

    Ah += bb * sAb + hh * sAh_;
    if (!SOFTA) Al += bb * sAb + hh * sAh_;
    if (SOFTA) {
        cm += (long)z * S_;  cd += (long)z * S_;
        pm += ((long)z * 16 + blockIdx.y) * S_;
    }
    Bh += bb * sBb + hh * sBh_;  Bl += bb * sBb + hh * sBh_;
    if (EPI == 0)      { Cf += bb * sCb + hh * sCh_; }
    else if (EPI == 1) { Ch += bb * sCb + hh * sCh_; }
    else               { Ch += bb * sCb + hh * sCh_; Cl += bb * sCb + hh * sCh_; }
    if (bias) bias += hh * sBiasH;

    uint4 areg4[2];
    auto issueA = [&](int c, int s) {
#pragma unroll
        for (int p = 0; p < 2; p++) {
            const int e = p * 256 + tid, r = e >> 2, ch = e & 3;
            const uint32_t off = (uint32_t)(r * 4 + (ch ^ ((r >> 1) & 3))) * 16;
            const long src = (long)(m0 + r) * lda + c * 32 + ch * 8;
            cpa16(smb + s * 16384 + off, Ah + src);
            cpa16(smb + s * 16384 + 8192 + off, Al + src);
        }
    };
    auto issueB = [&](int c, int s) {
#pragma unroll
        for (int p = 0; p < NT * 4 / 256; p++) {
            const int e = p * 256 + tid, r = e >> 2, ch = e & 3;
            const uint32_t off = (uint32_t)(r * 4 + (ch ^ ((r >> 1) & 3))) * 16;
            const long src = (long)(n0 + r) * ldb + c * 32 + ch * 8;
            cpa16(smb + BOFF + s * 2 * BSZ + off, Bh + src);
            cpa16(smb + BOFF + s * 2 * BSZ + BSZ + off, Bl + src);
        }
    };
    auto prefA = [&](int c) {   // SOFTA: load fp16 e' tile (128 x 32)
#pragma unroll
        for (int p = 0; p < 2; p++) {
            const int e = p * 256 + tid, r = e >> 2, j8 = (e & 3) * 8;
            areg4[p] = *(const uint4*)(Ah + (long)(m0 + r) * lda + c * 32 + j8);
        }
    };
    auto stsA = [&](int c, int s) {  // SOFTA: p = fp16(e' * scale_j), STS hi only
#pragma unroll
        for (int p = 0; p < 2; p++) {
            const int e = p * 256 + tid, r = e >> 2, j8 = (e & 3) * 8;
            const __half2* hp = (const __half2*)&areg4[p];
            uint4 hi;
            uint32_t* hw = (uint32_t*)&hi;
#pragma unroll
            for (int t = 0; t < 4; t++) {
                const float2 f = __half22float2(hp[t]);
                const __half2 ph = __floats2half2_rn(
                    f.x * scaleS[c & 1][j8 + 2 * t],
                    f.y * scaleS[c & 1][j8 + 2 * t + 1]);
                hw[t] = *(const uint32_t*)&ph;
            }
            const int ch = j8 >> 3;
            const uint32_t off = (uint32_t)(r * 4 + (ch ^ ((r >> 1) & 3))) * 16;
            *(uint4*)(sm + s * ASTG + off) = hi;
        }
    };

    // ldmatrix lane addressing
    const int rA = wm * 32 + (lane & 15);       // A rows
    const int cpA = (lane >> 4) & 1;
    const int swA = (rA >> 1) & 3;
    // B x4: lanes 0-7 matrix0 (nt, k-lo), 8-15 m1 (nt, k-hi),
    //       16-23 m2 (nt+1, k-lo), 24-31 m3 (nt+1, k-hi)
    const int rB4 = wn * WN + ((lane >> 4) & 1) * 8 + (lane & 7);
    const int cpB = (lane >> 3) & 1;
    const int swB = (rB4 >> 1) & 3;             // invariant under +16 row steps

    float acc[2][NB][4];
#pragma unroll
    for (int i = 0; i < 2; i++)
#pragma unroll
        for (int j = 0; j < NB; j++)
#pragma unroll
            for (int e = 0; e < 4; e++) acc[i][j][e] = 0.f;

    const int nch = K / 32;
    if (SOFTA) {
        prefA(0);
        if (tid < 32)
            scaleS[0][tid] = __expf(pm[tid] - cm[tid]) / cd[tid];
    } else {
        issueA(0, 0);
    }
    issueB(0, 0);
    CPC();
    if (SOFTA) __syncthreads();   // scaleS[0] visible before stsA(0)

    for (int c = 0; c < nch; c++) {
        const int s = c & 1;
        if (SOFTA) stsA(c, s);
        const bool more = (c + 1 < nch);
        if (more) {
            if (!SOFTA) issueA(c + 1, s ^ 1);
            issueB(c + 1, s ^ 1);
            CPC();
            if (SOFTA) prefA(c + 1);
            CPW1();
        } else {
            CPW0();
        }
        __syncthreads();

        if (SOFTA && more && tid < 32) {   // scale table for chunk c+1
            const int j = (c + 1) * 32 + tid;
            scaleS[s ^ 1][tid] = __expf(pm[j] - cm[j]) / cd[j];
        }

        const uint32_t aBase = smb + s * ASTG;
        const uint32_t bBase = smb + BOFF + s * 2 * BSZ;
#pragma unroll
        for (int ks = 0; ks < 2; ks++) {
            const int cA = (2 * ks + cpA) ^ swA;
            uint32_t ah0[4], ah1[4];
            ldm_x4(ah0, aBase + (rA * 4 + cA) * 16);
            ldm_x4(ah1, aBase + ((rA + 16) * 4 + cA) * 16);
            uint32_t al0[4], al1[4];
            if (!SOFTA) {
                ldm_x4(al0, aBase + 8192 + (rA * 4 + cA) * 16);
                ldm_x4(al1, aBase + 8192 + ((rA + 16) * 4 + cA) * 16);
            }
            const int cB = (2 * ks + cpB) ^ swB;
#pragma unroll
            for (int nt2 = 0; nt2 < NB / 2; nt2++) {
                uint32_t bh4[4], bl4[4];
                const uint32_t ob = ((uint32_t)(rB4 + nt2 * 16) * 4 + cB) * 16;
                ldm_x4(bh4, bBase + ob);
                ldm_x4(bl4, bBase + BSZ + ob);
                const int n0t = 2 * nt2;
                if (SOFTA) {
                    // wave 1: A*Bh across 4 accumulators; wave 2: A*Bl
                    mma_fp(acc[0][n0t],     ah0, bh4);
                    mma_fp(acc[1][n0t],     ah1, bh4);
                    mma_fp(acc[0][n0t + 1], ah0, bh4 + 2);
                    mma_fp(acc[1][n0t + 1], ah1, bh4 + 2);
                    mma_fp(acc[0][n0t],     ah0, bl4);
                    mma_fp(acc[1][n0t],     ah1, bl4);
                    mma_fp(acc[0][n0t + 1], ah0, bl4 + 2);
                    mma_fp(acc[1][n0t + 1], ah1, bl4 + 2);
                } else {
                    // waves: hh, hl, lh (per-acc order preserved)
                    mma16816(acc[0][n0t],     ah0, bh4);
                    mma16816(acc[1][n0t],     ah1, bh4);
                    mma16816(acc[0][n0t + 1], ah0, bh4 + 2);
                    mma16816(acc[1][n0t + 1], ah1, bh4 + 2);
                    mma16816(acc[0][n0t],     ah0, bl4);
                    mma16816(acc[1][n0t],     ah1, bl4);
                    mma16816(acc[0][n0t + 1], ah0, bl4 + 2);
                    mma16816(acc[1][n0t + 1], ah1, bl4 + 2);
                    mma16816(acc[0][n0t],     al0, bh4);
                    mma16816(acc[1][n0t],     al1, bh4);
                    mma16816(acc[0][n0t + 1], al0, bh4 + 2);
                    mma16816(acc[1][n0t + 1], al1, bh4 + 2);
                }
            }
        }
        __syncthreads();
    }

    // ---- epilogue ----
    const int gid = lane >> 2, qid = lane & 3;
    if (EPI == 1) {
        float* smM  = (float*)(sm + BOFF + 4 * BSZ);  // [4][128]
        float* smMF = smM + 512;                      // [128]
        float* smD  = smMF + 128;                     // [4][128]

        // 1: scale + mask into acc
#pragma unroll
        for (int mt = 0; mt < 2; mt++) {
            const int r0 = m0 + wm * 32 + mt * 16 + gid;
#pragma unroll
            for (int nt = 0; nt < NB; nt++) {
                const int col = n0 + wn * WN + nt * 8 + qid * 2;
                const int2 ma = *(const int2*)(mask + (long)r0 * S_ + col);
                const int2 mb = *(const int2*)(mask + (long)(r0 + 8) * S_ + col);
                acc[mt][nt][0] = ma.x ? acc[mt][nt][0] * scale : -10000.0f;
                acc[mt][nt][1] = ma.y ? acc[mt][nt][1] * scale : -10000.0f;
                acc[mt][nt][2] = mb.x ? acc[mt][nt][2] * scale : -10000.0f;
                acc[mt][nt][3] = mb.y ? acc[mt][nt][3] * scale : -10000.0f;
            }
        }
        // 2: per-tile column max over the 128 rows
#pragma unroll
        for (int nt = 0; nt < NB; nt++) {
            float mA = fmaxf(fmaxf(acc[0][nt][0], acc[0][nt][2]),
                             fmaxf(acc[1][nt][0], acc[1][nt][2]));
            float mB = fmaxf(fmaxf(acc[0][nt][1], acc[0][nt][3]),
                             fmaxf(acc[1][nt][1], acc[1][nt][3]));
#pragma unroll
            for (int d = 4; d <= 16; d <<= 1) {
                mA = fmaxf(mA, __shfl_xor_sync(0xffffffffu, mA, d));
                mB = fmaxf(mB, __shfl_xor_sync(0xffffffffu, mB, d));
            }
            if (gid == 0) {
                const int colL = wn * WN + nt * 8 + qid * 2;
                smM[wm * 128 + colL] = mA;
                smM[wm * 128 + colL + 1] = mB;
            }
        }
        __syncthreads();
        if (tid < 128) {
            smMF[tid] = fmaxf(fmaxf(smM[tid], smM[128 + tid]),
                              fmaxf(smM[256 + tid], smM[384 + tid]));
        }
        __syncthreads();
        // 3: e' = exp(s - m_tile): store fp16 + accumulate column sums
#pragma unroll
        for (int nt = 0; nt < NB; nt++) {
            const int colL = wn * WN + nt * 8 + qid * 2;
            const float MA = smMF[colL], MB = smMF[colL + 1];
            float sA = 0.f, sB = 0.f;
#pragma unroll
            for (int mt = 0; mt < 2; mt++) {
                const int r0 = m0 + wm * 32 + mt * 16 + gid;
                const float e0 = __expf(acc[mt][nt][0] - MA);
                const float e1 = __expf(acc[mt][nt][1] - MB);
                const float e2 = __expf(acc[mt][nt][2] - MA);
                const float e3 = __expf(acc[mt][nt][3] - MB);
                sA += e0 + e2;  sB += e1 + e3;
                const __half2 p01 = __floats2half2_rn(e0, e1);
                const __half2 p23 = __floats2half2_rn(e2, e3);
                *(uint32_t*)(Ch + (long)r0 * ldc + n0 + colL) = *(const uint32_t*)&p01;
                *(uint32_t*)(Ch + (long)(r0 + 8) * ldc + n0 + colL) = *(const uint32_t*)&p23;
            }
#pragma unroll
            for (int d = 4; d <= 16; d <<= 1) {
                sA += __shfl_xor_sync(0xffffffffu, sA, d);
                sB += __shfl_xor_sync(0xffffffffu, sB, d);
            }
            if (gid == 0) {
                smD[wm * 128 + colL] = sA;
                smD[wm * 128 + colL + 1] = sB;
            }
        }
        __syncthreads();
        if (tid < 128) {
            const float Dv = smD[tid] + smD[128 + tid] + smD[256 + tid] + smD[384 + tid];
            const long o = ((long)z * 16 + blockIdx.y) * S_ + n0 + tid;
            pm[o] = smMF[tid];
            pd[o] = Dv;
        }
    } else {
#pragma unroll
        for (int mt = 0; mt < 2; mt++) {
            const int r0 = m0 + wm * 32 + mt * 16 + gid;
#pragma unroll
            for (int nt = 0; nt < NB; nt++) {
                const int col = n0 + wn * WN + nt * 8 + qid * 2;
                float2 v0 = make_float2(acc[mt][nt][0], acc[mt][nt][1]);
                float2 v1 = make_float2(acc[mt][nt][2], acc[mt][nt][3]);
                if (bias) {
                    const float b0 = bias[col], b1 = bias[col + 1];
                    v0.x += b0; v0.y += b1; v1.x += b0; v1.y += b1;
                }
                if (EPI == 0) {
                    *(float2*)(Cf + (long)r0 * ldc + col) = v0;
                    *(float2*)(Cf + (long)(r0 + 8) * ldc + col) = v1;
                } else {
                    uint32_t h0, l0, h1, l1;
                    split2(v0.x, v0.y, h0, l0);
                    split2(v1.x, v1.y, h1, l1);
                    *(uint32_t*)(Ch + (long)r0 * ldc + col) = h0;
                    *(uint32_t*)(Cl + (long)r0 * ldc + col) = l0;
                    *(uint32_t*)(Ch + (long)(r0 + 8) * ldc + col) = h1;
                    *(uint32_t*)(Cl + (long)(r0 + 8) * ldc + col) = l1;
                }
            }
        }
    }
}

// ---- fp32 -> split bf16 preconversion, multi-tensor (grid.y = segment) ----
struct Cvt4 { const float* s[4]; };

__global__ __launch_bounds__(256)
void cvt_multi(Cvt4 a, u16* __restrict__ dh, u16* __restrict__ dl, long segElems4) {
    const int seg = blockIdx.y;
    const long i = (long)blockIdx.x * 256 + threadIdx.x;
    uint2 hh, ll;
    split4(((const float4*)a.s[seg])[i], hh, ll);
    ((uint2*)(dh))[seg * segElems4 + i] = hh;
    ((uint2*)(dl))[seg * segElems4 + i] = ll;
}

// ---- gather the three projection biases into one stride-indexed array ----
__global__ __launch_bounds__(256)
void biascopy(Cvt4 a, float* __restrict__ dst) {
    const int seg = blockIdx.y;
    const int i = blockIdx.x * 256 + threadIdx.x;
    dst[seg * D_ + i] = a.s[seg][i];
}

// ---- V transpose per head: split-bf16 in -> split-FP16 out ----
__global__ __launch_bounds__(256)
void vtrans_kernel(const u16* __restrict__ vh, const u16* __restrict__ vl,
                   u16* __restrict__ th, u16* __restrict__ tl) {
    __shared__ float t[64][65];
    const int z = blockIdx.y, jt = blockIdx.x * 64;
    const int b = z >> 4, h = z & 15;
    const long src = ((long)b * S_ + jt) * D_ + h * HD_;
    for (int i = threadIdx.x; i < 64 * 64; i += 256) {
        const long idx = src + (long)(i >> 6) * D_ + (i & 63);
        t[i >> 6][i & 63] = __bfloat162float(__ushort_as_bfloat16(vh[idx]))
                          + __bfloat162float(__ushort_as_bfloat16(vl[idx]));
    }
    __syncthreads();
    const long dst = (long)z * HD_ * S_ + jt;
    for (int i = threadIdx.x; i < 64 * 64; i += 256) {
        const float f = t[i & 63][i >> 6];
        const __half hi = __float2half_rn(f);
        const __half lo = __float2half_rn(f - __half2float(hi));
        const long o = dst + (long)(i >> 6) * S_ + (i & 63);
        th[o] = __half_as_ushort(hi);
        tl[o] = __half_as_ushort(lo);
    }
}

// ---- combine column-stats partials across the 16 i-tiles ----
__global__ __launch_bounds__(256)
void redstats_kernel(const float* __restrict__ pm, const float* __restrict__ pd,
                     float* __restrict__ cm, float* __restrict__ cd) {
    const int z = blockIdx.y;
    const int j = blockIdx.x * 256 + threadIdx.x;
    float m = -3.0e38f;
#pragma unroll
    for (int it = 0; it < 16; it++)
        m = fmaxf(m, pm[((long)z * 16 + it) * S_ + j]);
    float d = 0.f;
#pragma unroll
    for (int it = 0; it < 16; it++) {
        const long o = ((long)z * 16 + it) * S_ + j;
        d += pd[o] * __expf(pm[o] - m);
    }
    cm[z * S_ + j] = m;
    cd[z * S_ + j] = d;
}

// ---------------------------------------------------------------------------
extern "C" void kernel_launch(void* const* d_in, const int* in_sizes, int n_in,
                              void* d_out, int out_size)
{
    const float* query = (const float*)d_in[0];
    const float* key_  = (const float*)d_in[1];
    const float* value = (const float*)d_in[2];
    const int*   mask  = (const int*)d_in[3];
    const float* Wq = (const float*)d_in[4];
    const float* bq = (const float*)d_in[5];
    const float* Wk = (const float*)d_in[6];
    const float* bk = (const float*)d_in[7];
    const float* Wv = (const float*)d_in[8];
    const float* bv = (const float*)d_in[9];
    const float* Wp = (const float*)d_in[10];
    const float* bp = (const float*)d_in[11];
    float* out = (float*)d_out;

    u16 *p_cinh, *p_cinl, *p_winh, *p_winl, *p_pjh, *p_pjl;
    u16 *p_vth, *p_vtl, *p_ath, *p_atl, *p_e;
    float *p_b3, *ppm, *ppd, *pcm, *pcd;
    cudaGetSymbolAddress((void**)&p_cinh, cinh); cudaGetSymbolAddress((void**)&p_cinl, cinl);
    cudaGetSymbolAddress((void**)&p_winh, winh); cudaGetSymbolAddress((void**)&p_winl, winl);
    cudaGetSymbolAddress((void**)&p_pjh, pjh);   cudaGetSymbolAddress((void**)&p_pjl, pjl);
    cudaGetSymbolAddress((void**)&p_vth, vth);   cudaGetSymbolAddress((void**)&p_vtl, vtl);
    cudaGetSymbolAddress((void**)&p_ath, athA);  cudaGetSymbolAddress((void**)&p_atl, atlA);
    cudaGetSymbolAddress((void**)&p_e, g_e);
    cudaGetSymbolAddress((void**)&p_b3, bias3);
    cudaGetSymbolAddress((void**)&ppm, g_pm);  cudaGetSymbolAddress((void**)&ppd, g_pd);
    cudaGetSymbolAddress((void**)&pcm, g_cm);  cudaGetSymbolAddress((void**)&pcd, g_cd);

    const int SM_MAIN = 65536;           // NT=128 EPI 0/2 (bf16 3-term)
    const int SM_SCR  = 65536 + 4608;    // NT=128 EPI 1 (+stats)
    const int SM_PV   = 32768;           // NT=64 SOFTA (fp16 2-term)
    cudaFuncSetAttribute(mma_gemm<128, 2, false>, cudaFuncAttributeMaxDynamicSharedMemorySize, SM_MAIN);
    cudaFuncSetAttribute(mma_gemm<128, 0, false>, cudaFuncAttributeMaxDynamicSharedMemorySize, SM_MAIN);
    cudaFuncSetAttribute(mma_gemm<128, 1, false>, cudaFuncAttributeMaxDynamicSharedMemorySize, SM_SCR);
    cudaFuncSetAttribute(mma_gemm<64, 2, true>,   cudaFuncAttributeMaxDynamicSharedMemorySize, SM_PV);

    const long SD  = (long)S_ * D_;
    const long HSS = 16 * SSl;

    // 1) preconvert: inputs (3 segs), weights (4 segs), biases (3 segs)
    {
        Cvt4 ain; ain.s[0] = query; ain.s[1] = key_; ain.s[2] = value; ain.s[3] = nullptr;
        cvt_multi<<<dim3(MDsz / 1024, 3), 256>>>(ain, p_cinh, p_cinl, MDsz / 4);
        Cvt4 aw; aw.s[0] = Wq; aw.s[1] = Wk; aw.s[2] = Wv; aw.s[3] = Wp;
        cvt_multi<<<dim3(DDsz / 1024, 4), 256>>>(aw, p_winh, p_winl, DDsz / 4);
        Cvt4 ab; ab.s[0] = bq; ab.s[1] = bk; ab.s[2] = bv; ab.s[3] = nullptr;
        biascopy<<<dim3(D_ / 256, 3), 256>>>(ab, p_b3);
    }

    // 2) fused Q/K/V projections: one launch, z = 0..2 selects tensor set
    mma_gemm<128, 2, false><<<dim3(D_ / 128, M1_ / 128, 3), 256, SM_MAIN>>>(
        p_cinh, p_cinl, p_winh, p_winl,
        nullptr, p_pjh, p_pjl, p_b3, nullptr, nullptr, nullptr, nullptr, nullptr,
        D_, D_, D_, D_,
        0, MDsz, 0, DDsz, 0, MDsz, D_, 0.f);

    // 3) V transpose per head (V = projection segment 2) -> split fp16
    vtrans_kernel<<<dim3(S_ / 64, BHN), 256>>>(p_pjh + 2 * MDsz, p_pjl + 2 * MDsz,
                                               p_vth, p_vtl);

    // 4) scores = 0.25 * q k^T, mask -> e' fp16 + column-stats partials
    mma_gemm<128, 1, false><<<dim3(S_ / 128, S_ / 128, BHN), 256, SM_SCR>>>(
        p_pjh, p_pjl, p_pjh + MDsz, p_pjl + MDsz,
        nullptr, p_e, nullptr, nullptr, mask, nullptr, nullptr, ppm, ppd,
        D_, D_, S_, HD_, SD, HD_, SD, HD_, HSS, SSl, 0, 0.25f);

    // 5) reduce partials -> cm, cd
    redstats_kernel<<<dim3(S_ / 256, BHN), 256>>>(ppm, ppd, pcm, pcd);

    // 6) attn @ V : fp16 mma 2-term (A = fp16 e'*scale, B = V^T split fp16)
    mma_gemm<64, 2, true><<<dim3(1, S_ / 128, BHN), 256, SM_PV>>>(
        p_e, nullptr, p_vth, p_vtl,
        nullptr, p_ath, p_atl, nullptr, nullptr, pcm, pcd, ppm, nullptr,
        S_, S_, D_, S_, HSS, SSl, (long)16 * HD_ * S_, (long)HD_ * S_, SD, HD_, 0, 0.f);

    // 7) output projection -> d_out (fp32 + bias, weight segment 3)
    mma_gemm<128, 0, false><<<dim3(D_ / 128, M1_ / 128, 1), 256, SM_MAIN>>>(
        p_ath, p_atl, p_winh + 3 * DDsz, p_winl + 3 * DDsz,
        out, nullptr, nullptr, bp, nullptr, nullptr, nullptr, nullptr, nullptr,
        D_, D_, D_, D_, 0, 0, 0, 0, 0, 0, 0, 0.f);
}

// round 17
// speedup vs baseline: 1.1146x; 1.0321x over previous
#include <cuda_runtime.h>
#include <cuda_bf16.h>
#include <cuda_fp16.h>
#include <stdint.h>

#define S_  2048
#define D_  1024
#define HD_ 64
#define M1_ 4096
#define BHN 32
#define SSl ((long)S_ * S_)

typedef unsigned short u16;

#define MDsz ((long)M1_ * D_)
#define DDsz ((long)D_ * D_)

// ---------------- static scratch ----------------
__device__ u16 cinh[3 * MDsz], cinl[3 * MDsz];   // converted inputs (q,k,v)
__device__ u16 winh[4 * DDsz], winl[4 * DDsz];   // converted weights (wq,wk,wv,wp)
__device__ float bias3[3 * D_];                  // gathered bq,bk,bv
__device__ u16 pjh[3 * MDsz], pjl[3 * MDsz];     // projected q,k,v (split bf16)
__device__ u16 vth[BHN * HD_ * S_];              // V^T per head (single fp16)
__device__ u16 athA[MDsz], atlA[MDsz];           // attn output (split bf16)
__device__ u16 g_e[(long)BHN * SSl];             // e' = exp(s - m_tile), fp16
__device__ float g_pm[BHN * 16 * S_], g_pd[BHN * 16 * S_];
__device__ float g_cm[BHN * S_], g_cd[BHN * S_];

// ---------------- helpers ----------------
__device__ __forceinline__ uint32_t smem_u32(const void* p) {
    uint32_t a;
    asm("{ .reg .u64 t; cvta.to.shared.u64 t, %1; cvt.u32.u64 %0, t; }" : "=r"(a) : "l"(p));
    return a;
}
__device__ __forceinline__ void cpa16(uint32_t d, const void* s) {
    asm volatile("cp.async.cg.shared.global [%0], [%1], 16;" :: "r"(d), "l"(s));
}
#define CPC()  asm volatile("cp.async.commit_group;" ::: "memory")
#define CPW1() asm volatile("cp.async.wait_group 1;" ::: "memory")
#define CPW0() asm volatile("cp.async.wait_group 0;" ::: "memory")

__device__ __forceinline__ void ldm_x4(uint32_t* r, uint32_t addr) {
    asm volatile("ldmatrix.sync.aligned.m8n8.x4.shared.b16 {%0,%1,%2,%3}, [%4];"
                 : "=r"(r[0]), "=r"(r[1]), "=r"(r[2]), "=r"(r[3]) : "r"(addr));
}
__device__ __forceinline__ void mma16816(float* c, const uint32_t* a, const uint32_t* b) {
    asm volatile(
        "mma.sync.aligned.m16n8k16.row.col.f32.bf16.bf16.f32 "
        "{%0,%1,%2,%3}, {%4,%5,%6,%7}, {%8,%9}, {%0,%1,%2,%3};"
        : "+f"(c[0]), "+f"(c[1]), "+f"(c[2]), "+f"(c[3])
        : "r"(a[0]), "r"(a[1]), "r"(a[2]), "r"(a[3]), "r"(b[0]), "r"(b[1]));
}
__device__ __forceinline__ void mma_fp(float* c, const uint32_t* a, const uint32_t* b) {
    asm volatile(
        "mma.sync.aligned.m16n8k16.row.col.f32.f16.f16.f32 "
        "{%0,%1,%2,%3}, {%4,%5,%6,%7}, {%8,%9}, {%0,%1,%2,%3};"
        : "+f"(c[0]), "+f"(c[1]), "+f"(c[2]), "+f"(c[3])
        : "r"(a[0]), "r"(a[1]), "r"(a[2]), "r"(a[3]), "r"(b[0]), "r"(b[1]));
}
__device__ __forceinline__ uint32_t pk2(float a, float b) {
    __nv_bfloat162 t = __floats2bfloat162_rn(a, b);
    return *(uint32_t*)&t;
}
__device__ __forceinline__ void split2(float a, float b, uint32_t& h, uint32_t& l) {
    __nv_bfloat16 h0 = __float2bfloat16(a), h1 = __float2bfloat16(b);
    h = ((uint32_t)__bfloat16_as_ushort(h1) << 16) | __bfloat16_as_ushort(h0);
    l = pk2(a - __bfloat162float(h0), b - __bfloat162float(h1));
}
__device__ __forceinline__ void split4(float4 v, uint2& h, uint2& l) {
    split2(v.x, v.y, h.x, l.x);
    split2(v.z, v.w, h.y, l.y);
}

// ---------------------------------------------------------------------------
// 2-stage pipelined mma.sync GEMM (proven R11/R16 structure).
// !SOFTA (bf16 3-term): C ~= AhBh + AhBl + AlBh, A/B preconverted split-bf16.
// SOFTA  (fp16 1-term B): A = fp16 e' (in Ah); p = fp16(e' * scale_j);
//        B = V^T single fp16; C ~= A*Bh only.  PV MMA count halved vs R16.
// EPI 0: fp32 out + bias; 1: scores -> fp16 e' out + column stats partials;
//     2: split-bf16 out (+bias)
// ---------------------------------------------------------------------------
template<int NT, int EPI, bool SOFTA>
__global__ __launch_bounds__(256, 2)
void mma_gemm(const u16* __restrict__ Ah, const u16* __restrict__ Al,
              const u16* __restrict__ Bh, const u16* __restrict__ Bl,
              float* __restrict__ Cf, u16* __restrict__ Ch, u16* __restrict__ Cl,
              const float* __restrict__ bias, const int* __restrict__ mask,
              const float* __restrict__ cm, const float* __restrict__ cd,
              float* __restrict__ pm, float* __restrict__ pd,
              int lda, int ldb, int ldc, int K,
              long sAb, long sAh_, long sBb, long sBh_, long sCb, long sCh_,
              long sBiasH, float scale)
{
    constexpr int WN  = NT / 2;
    constexpr int NB  = WN / 8;
    constexpr int BSZ = NT * 64;                   // bytes per B array per stage
    constexpr int ASTG = SOFTA ? 8192 : 16384;     // A bytes per stage
    constexpr int BOFF = 2 * ASTG;                 // A region size
    extern __shared__ __align__(128) uint8_t sm[];
    __shared__ float scaleS[2][32];
    const uint32_t smb = smem_u32(sm);

    const int tid = threadIdx.x, wid = tid >> 5, lane = tid & 31;
    const int wm = wid >> 1, wn = wid & 1;
    const int z = blockIdx.z, bb = z >> 4, hh = z & 15;
    const int m0 = blockIdx.y * 128, n0 = blockIdx.x * NT;

    Ah += bb * sAb + hh * sAh_;
    if (!SOFTA) Al += bb * sAb + hh * sAh_;
    if (SOFTA) {
        cm += (long)z * S_;  cd += (long)z * S_;
        pm += ((long)z * 16 + blockIdx.y) * S_;
    }
    Bh += bb * sBb + hh * sBh_;
    if (!SOFTA) Bl += bb * sBb + hh * sBh_;
    if (EPI == 0)      { Cf += bb * sCb + hh * sCh_; }
    else if (EPI == 1) { Ch += bb * sCb + hh * sCh_; }
    else               { Ch += bb * sCb + hh * sCh_; Cl += bb * sCb + hh * sCh_; }
    if (bias) bias += hh * sBiasH;

    uint4 areg4[2];
    auto issueA = [&](int c, int s) {
#pragma unroll
        for (int p = 0; p < 2; p++) {
            const int e = p * 256 + tid, r = e >> 2, ch = e & 3;
            const uint32_t off = (uint32_t)(r * 4 + (ch ^ ((r >> 1) & 3))) * 16;
            const long src = (long)(m0 + r) * lda + c * 32 + ch * 8;
            cpa16(smb + s * 16384 + off, Ah + src);
            cpa16(smb + s * 16384 + 8192 + off, Al + src);
        }
    };
    auto issueB = [&](int c, int s) {
#pragma unroll
        for (int p = 0; p < NT * 4 / 256; p++) {
            const int e = p * 256 + tid, r = e >> 2, ch = e & 3;
            const uint32_t off = (uint32_t)(r * 4 + (ch ^ ((r >> 1) & 3))) * 16;
            const long src = (long)(n0 + r) * ldb + c * 32 + ch * 8;
            cpa16(smb + BOFF + s * 2 * BSZ + off, Bh + src);
            if (!SOFTA)
                cpa16(smb + BOFF + s * 2 * BSZ + BSZ + off, Bl + src);
        }
    };
    auto prefA = [&](int c) {   // SOFTA: load fp16 e' tile (128 x 32)
#pragma unroll
        for (int p = 0; p < 2; p++) {
            const int e = p * 256 + tid, r = e >> 2, j8 = (e & 3) * 8;
            areg4[p] = *(const uint4*)(Ah + (long)(m0 + r) * lda + c * 32 + j8);
        }
    };
    auto stsA = [&](int c, int s) {  // SOFTA: p = fp16(e' * scale_j), STS hi only
#pragma unroll
        for (int p = 0; p < 2; p++) {
            const int e = p * 256 + tid, r = e >> 2, j8 = (e & 3) * 8;
            const __half2* hp = (const __half2*)&areg4[p];
            uint4 hi;
            uint32_t* hw = (uint32_t*)&hi;
#pragma unroll
            for (int t = 0; t < 4; t++) {
                const float2 f = __half22float2(hp[t]);
                const __half2 ph = __floats2half2_rn(
                    f.x * scaleS[c & 1][j8 + 2 * t],
                    f.y * scaleS[c & 1][j8 + 2 * t + 1]);
                hw[t] = *(const uint32_t*)&ph;
            }
            const int ch = j8 >> 3;
            const uint32_t off = (uint32_t)(r * 4 + (ch ^ ((r >> 1) & 3))) * 16;
            *(uint4*)(sm + s * ASTG + off) = hi;
        }
    };

    // ldmatrix lane addressing
    const int rA = wm * 32 + (lane & 15);       // A rows
    const int cpA = (lane >> 4) & 1;
    const int swA = (rA >> 1) & 3;
    // B x4: lanes 0-7 matrix0 (nt, k-lo), 8-15 m1 (nt, k-hi),
    //       16-23 m2 (nt+1, k-lo), 24-31 m3 (nt+1, k-hi)
    const int rB4 = wn * WN + ((lane >> 4) & 1) * 8 + (lane & 7);
    const int cpB = (lane >> 3) & 1;
    const int swB = (rB4 >> 1) & 3;             // invariant under +16 row steps

    float acc[2][NB][4];
#pragma unroll
    for (int i = 0; i < 2; i++)
#pragma unroll
        for (int j = 0; j < NB; j++)
#pragma unroll
            for (int e = 0; e < 4; e++) acc[i][j][e] = 0.f;

    const int nch = K / 32;
    if (SOFTA) {
        prefA(0);
        if (tid < 32)
            scaleS[0][tid] = __expf(pm[tid] - cm[tid]) / cd[tid];
    } else {
        issueA(0, 0);
    }
    issueB(0, 0);
    CPC();
    if (SOFTA) __syncthreads();   // scaleS[0] visible before stsA(0)

    for (int c = 0; c < nch; c++) {
        const int s = c & 1;
        if (SOFTA) stsA(c, s);
        const bool more = (c + 1 < nch);
        if (more) {
            if (!SOFTA) issueA(c + 1, s ^ 1);
            issueB(c + 1, s ^ 1);
            CPC();
            if (SOFTA) prefA(c + 1);
            CPW1();
        } else {
            CPW0();
        }
        __syncthreads();

        if (SOFTA && more && tid < 32) {   // scale table for chunk c+1
            const int j = (c + 1) * 32 + tid;
            scaleS[s ^ 1][tid] = __expf(pm[j] - cm[j]) / cd[j];
        }

        const uint32_t aBase = smb + s * ASTG;
        const uint32_t bBase = smb + BOFF + s * 2 * BSZ;
#pragma unroll
        for (int ks = 0; ks < 2; ks++) {
            const int cA = (2 * ks + cpA) ^ swA;
            uint32_t ah0[4], ah1[4];
            ldm_x4(ah0, aBase + (rA * 4 + cA) * 16);
            ldm_x4(ah1, aBase + ((rA + 16) * 4 + cA) * 16);
            uint32_t al0[4], al1[4];
            if (!SOFTA) {
                ldm_x4(al0, aBase + 8192 + (rA * 4 + cA) * 16);
                ldm_x4(al1, aBase + 8192 + ((rA + 16) * 4 + cA) * 16);
            }
            const int cB = (2 * ks + cpB) ^ swB;
#pragma unroll
            for (int nt2 = 0; nt2 < NB / 2; nt2++) {
                uint32_t bh4[4];
                const uint32_t ob = ((uint32_t)(rB4 + nt2 * 16) * 4 + cB) * 16;
                ldm_x4(bh4, bBase + ob);
                const int n0t = 2 * nt2;
                if (SOFTA) {
                    // single term: A*Bh across 4 accumulators
                    mma_fp(acc[0][n0t],     ah0, bh4);
                    mma_fp(acc[1][n0t],     ah1, bh4);
                    mma_fp(acc[0][n0t + 1], ah0, bh4 + 2);
                    mma_fp(acc[1][n0t + 1], ah1, bh4 + 2);
                } else {
                    uint32_t bl4[4];
                    ldm_x4(bl4, bBase + BSZ + ob);
                    // waves: hh, hl, lh (per-acc order preserved)
                    mma16816(acc[0][n0t],     ah0, bh4);
                    mma16816(acc[1][n0t],     ah1, bh4);
                    mma16816(acc[0][n0t + 1], ah0, bh4 + 2);
                    mma16816(acc[1][n0t + 1], ah1, bh4 + 2);
                    mma16816(acc[0][n0t],     ah0, bl4);
                    mma16816(acc[1][n0t],     ah1, bl4);
                    mma16816(acc[0][n0t + 1], ah0, bl4 + 2);
                    mma16816(acc[1][n0t + 1], ah1, bl4 + 2);
                    mma16816(acc[0][n0t],     al0, bh4);
                    mma16816(acc[1][n0t],     al1, bh4);
                    mma16816(acc[0][n0t + 1], al0, bh4 + 2);
                    mma16816(acc[1][n0t + 1], al1, bh4 + 2);
                }
            }
        }
        __syncthreads();
    }

    // ---- epilogue ----
    const int gid = lane >> 2, qid = lane & 3;
    if (EPI == 1) {
        float* smM  = (float*)(sm + BOFF + 4 * BSZ);  // [4][128]
        float* smMF = smM + 512;                      // [128]
        float* smD  = smMF + 128;                     // [4][128]

        // 1: scale + mask into acc
#pragma unroll
        for (int mt = 0; mt < 2; mt++) {
            const int r0 = m0 + wm * 32 + mt * 16 + gid;
#pragma unroll
            for (int nt = 0; nt < NB; nt++) {
                const int col = n0 + wn * WN + nt * 8 + qid * 2;
                const int2 ma = *(const int2*)(mask + (long)r0 * S_ + col);
                const int2 mb = *(const int2*)(mask + (long)(r0 + 8) * S_ + col);
                acc[mt][nt][0] = ma.x ? acc[mt][nt][0] * scale : -10000.0f;
                acc[mt][nt][1] = ma.y ? acc[mt][nt][1] * scale : -10000.0f;
                acc[mt][nt][2] = mb.x ? acc[mt][nt][2] * scale : -10000.0f;
                acc[mt][nt][3] = mb.y ? acc[mt][nt][3] * scale : -10000.0f;
            }
        }
        // 2: per-tile column max over the 128 rows
#pragma unroll
        for (int nt = 0; nt < NB; nt++) {
            float mA = fmaxf(fmaxf(acc[0][nt][0], acc[0][nt][2]),
                             fmaxf(acc[1][nt][0], acc[1][nt][2]));
            float mB = fmaxf(fmaxf(acc[0][nt][1], acc[0][nt][3]),
                             fmaxf(acc[1][nt][1], acc[1][nt][3]));
#pragma unroll
            for (int d = 4; d <= 16; d <<= 1) {
                mA = fmaxf(mA, __shfl_xor_sync(0xffffffffu, mA, d));
                mB = fmaxf(mB, __shfl_xor_sync(0xffffffffu, mB, d));
            }
            if (gid == 0) {
                const int colL = wn * WN + nt * 8 + qid * 2;
                smM[wm * 128 + colL] = mA;
                smM[wm * 128 + colL + 1] = mB;
            }
        }
        __syncthreads();
        if (tid < 128) {
            smMF[tid] = fmaxf(fmaxf(smM[tid], smM[128 + tid]),
                              fmaxf(smM[256 + tid], smM[384 + tid]));
        }
        __syncthreads();
        // 3: e' = exp(s - m_tile): store fp16 + accumulate column sums
#pragma unroll
        for (int nt = 0; nt < NB; nt++) {
            const int colL = wn * WN + nt * 8 + qid * 2;
            const float MA = smMF[colL], MB = smMF[colL + 1];
            float sA = 0.f, sB = 0.f;
#pragma unroll
            for (int mt = 0; mt < 2; mt++) {
                const int r0 = m0 + wm * 32 + mt * 16 + gid;
                const float e0 = __expf(acc[mt][nt][0] - MA);
                const float e1 = __expf(acc[mt][nt][1] - MB);
                const float e2 = __expf(acc[mt][nt][2] - MA);
                const float e3 = __expf(acc[mt][nt][3] - MB);
                sA += e0 + e2;  sB += e1 + e3;
                const __half2 p01 = __floats2half2_rn(e0, e1);
                const __half2 p23 = __floats2half2_rn(e2, e3);
                *(uint32_t*)(Ch + (long)r0 * ldc + n0 + colL) = *(const uint32_t*)&p01;
                *(uint32_t*)(Ch + (long)(r0 + 8) * ldc + n0 + colL) = *(const uint32_t*)&p23;
            }
#pragma unroll
            for (int d = 4; d <= 16; d <<= 1) {
                sA += __shfl_xor_sync(0xffffffffu, sA, d);
                sB += __shfl_xor_sync(0xffffffffu, sB, d);
            }
            if (gid == 0) {
                smD[wm * 128 + colL] = sA;
                smD[wm * 128 + colL + 1] = sB;
            }
        }
        __syncthreads();
        if (tid < 128) {
            const float Dv = smD[tid] + smD[128 + tid] + smD[256 + tid] + smD[384 + tid];
            const long o = ((long)z * 16 + blockIdx.y) * S_ + n0 + tid;
            pm[o] = smMF[tid];
            pd[o] = Dv;
        }
    } else {
#pragma unroll
        for (int mt = 0; mt < 2; mt++) {
            const int r0 = m0 + wm * 32 + mt * 16 + gid;
#pragma unroll
            for (int nt = 0; nt < NB; nt++) {
                const int col = n0 + wn * WN + nt * 8 + qid * 2;
                float2 v0 = make_float2(acc[mt][nt][0], acc[mt][nt][1]);
                float2 v1 = make_float2(acc[mt][nt][2], acc[mt][nt][3]);
                if (bias) {
                    const float b0 = bias[col], b1 = bias[col + 1];
                    v0.x += b0; v0.y += b1; v1.x += b0; v1.y += b1;
                }
                if (EPI == 0) {
                    *(float2*)(Cf + (long)r0 * ldc + col) = v0;
                    *(float2*)(Cf + (long)(r0 + 8) * ldc + col) = v1;
                } else {
                    uint32_t h0, l0, h1, l1;
                    split2(v0.x, v0.y, h0, l0);
                    split2(v1.x, v1.y, h1, l1);
                    *(uint32_t*)(Ch + (long)r0 * ldc + col) = h0;
                    *(uint32_t*)(Cl + (long)r0 * ldc + col) = l0;
                    *(uint32_t*)(Ch + (long)(r0 + 8) * ldc + col) = h1;
                    *(uint32_t*)(Cl + (long)(r0 + 8) * ldc + col) = l1;
                }
            }
        }
    }
}

// ---- fp32 -> split bf16 preconversion, multi-tensor (grid.y = segment) ----
struct Cvt4 { const float* s[4]; };

__global__ __launch_bounds__(256)
void cvt_multi(Cvt4 a, u16* __restrict__ dh, u16* __restrict__ dl, long segElems4) {
    const int seg = blockIdx.y;
    const long i = (long)blockIdx.x * 256 + threadIdx.x;
    uint2 hh, ll;
    split4(((const float4*)a.s[seg])[i], hh, ll);
    ((uint2*)(dh))[seg * segElems4 + i] = hh;
    ((uint2*)(dl))[seg * segElems4 + i] = ll;
}

// ---- gather the three projection biases into one stride-indexed array ----
__global__ __launch_bounds__(256)
void biascopy(Cvt4 a, float* __restrict__ dst) {
    const int seg = blockIdx.y;
    const int i = blockIdx.x * 256 + threadIdx.x;
    dst[seg * D_ + i] = a.s[seg][i];
}

// ---- V transpose per head: split-bf16 in -> single FP16 out ----
__global__ __launch_bounds__(256)
void vtrans_kernel(const u16* __restrict__ vh, const u16* __restrict__ vl,
                   u16* __restrict__ th) {
    __shared__ float t[64][65];
    const int z = blockIdx.y, jt = blockIdx.x * 64;
    const int b = z >> 4, h = z & 15;
    const long src = ((long)b * S_ + jt) * D_ + h * HD_;
    for (int i = threadIdx.x; i < 64 * 64; i += 256) {
        const long idx = src + (long)(i >> 6) * D_ + (i & 63);
        t[i >> 6][i & 63] = __bfloat162float(__ushort_as_bfloat16(vh[idx]))
                          + __bfloat162float(__ushort_as_bfloat16(vl[idx]));
    }
    __syncthreads();
    const long dst = (long)z * HD_ * S_ + jt;
    for (int i = threadIdx.x; i < 64 * 64; i += 256) {
        const long o = dst + (long)(i >> 6) * S_ + (i & 63);
        th[o] = __half_as_ushort(__float2half_rn(t[i & 63][i >> 6]));
    }
}

// ---- combine column-stats partials across the 16 i-tiles ----
__global__ __launch_bounds__(256)
void redstats_kernel(const float* __restrict__ pm, const float* __restrict__ pd,
                     float* __restrict__ cm, float* __restrict__ cd) {
    const int z = blockIdx.y;
    const int j = blockIdx.x * 256 + threadIdx.x;
    float m = -3.0e38f;
#pragma unroll
    for (int it = 0; it < 16; it++)
        m = fmaxf(m, pm[((long)z * 16 + it) * S_ + j]);
    float d = 0.f;
#pragma unroll
    for (int it = 0; it < 16; it++) {
        const long o = ((long)z * 16 + it) * S_ + j;
        d += pd[o] * __expf(pm[o] - m);
    }
    cm[z * S_ + j] = m;
    cd[z * S_ + j] = d;
}

// ---------------------------------------------------------------------------
extern "C" void kernel_launch(void* const* d_in, const int* in_sizes, int n_in,
                              void* d_out, int out_size)
{
    const float* query = (const float*)d_in[0];
    const float* key_  = (const float*)d_in[1];
    const float* value = (const float*)d_in[2];
    const int*   mask  = (const int*)d_in[3];
    const float* Wq = (const float*)d_in[4];
    const float* bq = (const float*)d_in[5];
    const float* Wk = (const float*)d_in[6];
    const float* bk = (const float*)d_in[7];
    const float* Wv = (const float*)d_in[8];
    const float* bv = (const float*)d_in[9];
    const float* Wp = (const float*)d_in[10];
    const float* bp = (const float*)d_in[11];
    float* out = (float*)d_out;

    u16 *p_cinh, *p_cinl, *p_winh, *p_winl, *p_pjh, *p_pjl;
    u16 *p_vth, *p_ath, *p_atl, *p_e;
    float *p_b3, *ppm, *ppd, *pcm, *pcd;
    cudaGetSymbolAddress((void**)&p_cinh, cinh); cudaGetSymbolAddress((void**)&p_cinl, cinl);
    cudaGetSymbolAddress((void**)&p_winh, winh); cudaGetSymbolAddress((void**)&p_winl, winl);
    cudaGetSymbolAddress((void**)&p_pjh, pjh);   cudaGetSymbolAddress((void**)&p_pjl, pjl);
    cudaGetSymbolAddress((void**)&p_vth, vth);
    cudaGetSymbolAddress((void**)&p_ath, athA);  cudaGetSymbolAddress((void**)&p_atl, atlA);
    cudaGetSymbolAddress((void**)&p_e, g_e);
    cudaGetSymbolAddress((void**)&p_b3, bias3);
    cudaGetSymbolAddress((void**)&ppm, g_pm);  cudaGetSymbolAddress((void**)&ppd, g_pd);
    cudaGetSymbolAddress((void**)&pcm, g_cm);  cudaGetSymbolAddress((void**)&pcd, g_cd);

    const int SM_MAIN = 65536;           // NT=128 EPI 0/2 (bf16 3-term)
    const int SM_SCR  = 65536 + 4608;    // NT=128 EPI 1 (+stats)
    const int SM_PV   = 32768;           // NT=64 SOFTA (fp16 1-term B)
    cudaFuncSetAttribute(mma_gemm<128, 2, false>, cudaFuncAttributeMaxDynamicSharedMemorySize, SM_MAIN);
    cudaFuncSetAttribute(mma_gemm<128, 0, false>, cudaFuncAttributeMaxDynamicSharedMemorySize, SM_MAIN);
    cudaFuncSetAttribute(mma_gemm<128, 1, false>, cudaFuncAttributeMaxDynamicSharedMemorySize, SM_SCR);
    cudaFuncSetAttribute(mma_gemm<64, 2, true>,   cudaFuncAttributeMaxDynamicSharedMemorySize, SM_PV);

    const long SD  = (long)S_ * D_;
    const long HSS = 16 * SSl;

    // 1) preconvert: inputs (3 segs), weights (4 segs), biases (3 segs)
    {
        Cvt4 ain; ain.s[0] = query; ain.s[1] = key_; ain.s[2] = value; ain.s[3] = nullptr;
        cvt_multi<<<dim3(MDsz / 1024, 3), 256>>>(ain, p_cinh, p_cinl, MDsz / 4);
        Cvt4 aw; aw.s[0] = Wq; aw.s[1] = Wk; aw.s[2] = Wv; aw.s[3] = Wp;
        cvt_multi<<<dim3(DDsz / 1024, 4), 256>>>(aw, p_winh, p_winl, DDsz / 4);
        Cvt4 ab; ab.s[0] = bq; ab.s[1] = bk; ab.s[2] = bv; ab.s[3] = nullptr;
        biascopy<<<dim3(D_ / 256, 3), 256>>>(ab, p_b3);
    }

    // 2) fused Q/K/V projections: one launch, z = 0..2 selects tensor set
    mma_gemm<128, 2, false><<<dim3(D_ / 128, M1_ / 128, 3), 256, SM_MAIN>>>(
        p_cinh, p_cinl, p_winh, p_winl,
        nullptr, p_pjh, p_pjl, p_b3, nullptr, nullptr, nullptr, nullptr, nullptr,
        D_, D_, D_, D_,
        0, MDsz, 0, DDsz, 0, MDsz, D_, 0.f);

    // 3) V transpose per head (V = projection segment 2) -> single fp16
    vtrans_kernel<<<dim3(S_ / 64, BHN), 256>>>(p_pjh + 2 * MDsz, p_pjl + 2 * MDsz,
                                               p_vth);

    // 4) scores = 0.25 * q k^T, mask -> e' fp16 + column-stats partials
    mma_gemm<128, 1, false><<<dim3(S_ / 128, S_ / 128, BHN), 256, SM_SCR>>>(
        p_pjh, p_pjl, p_pjh + MDsz, p_pjl + MDsz,
        nullptr, p_e, nullptr, nullptr, mask, nullptr, nullptr, ppm, ppd,
        D_, D_, S_, HD_, SD, HD_, SD, HD_, HSS, SSl, 0, 0.25f);

    // 5) reduce partials -> cm, cd
    redstats_kernel<<<dim3(S_ / 256, BHN), 256>>>(ppm, ppd, pcm, pcd);

    // 6) attn @ V : fp16 mma 1-term (A = fp16 e'*scale, B = V^T fp16)
    mma_gemm<64, 2, true><<<dim3(1, S_ / 128, BHN), 256, SM_PV>>>(
        p_e, nullptr, p_vth, nullptr,
        nullptr, p_ath, p_atl, nullptr, nullptr, pcm, pcd, ppm, nullptr,
        S_, S_, D_, S_, HSS, SSl, (long)16 * HD_ * S_, (long)HD_ * S_, SD, HD_, 0, 0.f);

    // 7) output projection -> d_out (fp32 + bias, weight segment 3)
    mma_gemm<128, 0, false><<<dim3(D_ / 128, M1_ / 128, 1), 256, SM_MAIN>>>(
        p_ath, p_atl, p_winh + 3 * DDsz, p_winl + 3 * DDsz,
        out, nullptr, nullptr, bp, nullptr, nullptr, nullptr, nullptr, nullptr,
        D_, D_, D_, D_, 0, 0, 0, 0, 0, 0, 0, 0.f);
}